// round 1
// baseline (speedup 1.0000x reference)
#include <cuda_runtime.h>
#include <math.h>

// Problem constants
#define B_  128
#define T_  64
#define F_  2048
#define N_  1024
#define H_  1024
#define C_  22
#define G4  (4 * H_)   // 4096

// ---------------- scratch (static device globals; no allocation) ----------------
__device__ float g_z [(size_t)B_ * T_ * N_];    // [8192, 1024]  32 MB
__device__ float g_xg[(size_t)B_ * T_ * G4];    // [128, 64, 4096] 128 MB
__device__ float g_gates[(size_t)B_ * G4];      // [128, 4096]   2 MB
__device__ float g_h [(size_t)B_ * H_];         // [128, 1024]
__device__ float g_c [(size_t)B_ * H_];
__device__ float g_hs[(size_t)T_ * B_ * H_];    // [64, 128, 1024] 32 MB

// ---------------- generic NT GEMM: C[m,n] = sum_k A[m,k] * B[n,k] (+epilogue) ----
// A: M x K row-major, Bw: N x K row-major.
// epi: 0 = +bias ; 1 = relu(+bias) ; 2 = +bias + add[row*addStride + col]
template <int BM, int BN, int BK, int TM, int TN>
__global__ void gemm_nt(const float* __restrict__ A,
                        const float* __restrict__ Bw,
                        const float* __restrict__ bias,
                        const float* __restrict__ add,
                        float* __restrict__ C,
                        int M, int N, int K,
                        int epi, long addStride)
{
    constexpr int NT = (BM / TM) * (BN / TN);
    __shared__ __align__(16) float As[BK][BM];
    __shared__ __align__(16) float Bs[BK][BN];

    const int tid = threadIdx.x;
    const int bm = blockIdx.y * BM;
    const int bn = blockIdx.x * BN;
    const int tx = tid % (BN / TN);
    const int ty = tid / (BN / TN);

    float acc[TM][TN];
#pragma unroll
    for (int i = 0; i < TM; i++)
#pragma unroll
        for (int j = 0; j < TN; j++) acc[i][j] = 0.f;

    for (int k0 = 0; k0 < K; k0 += BK) {
        // load A tile (BM x BK) transposed into As[BK][BM]
#pragma unroll
        for (int i = tid; i < BM * BK / 4; i += NT) {
            int row = i / (BK / 4);
            int kc  = (i % (BK / 4)) * 4;
            float4 v = *reinterpret_cast<const float4*>(
                &A[(size_t)(bm + row) * K + k0 + kc]);
            As[kc + 0][row] = v.x;
            As[kc + 1][row] = v.y;
            As[kc + 2][row] = v.z;
            As[kc + 3][row] = v.w;
        }
        // load B tile (BN x BK) transposed into Bs[BK][BN]
#pragma unroll
        for (int i = tid; i < BN * BK / 4; i += NT) {
            int row = i / (BK / 4);
            int kc  = (i % (BK / 4)) * 4;
            float4 v = *reinterpret_cast<const float4*>(
                &Bw[(size_t)(bn + row) * K + k0 + kc]);
            Bs[kc + 0][row] = v.x;
            Bs[kc + 1][row] = v.y;
            Bs[kc + 2][row] = v.z;
            Bs[kc + 3][row] = v.w;
        }
        __syncthreads();

#pragma unroll
        for (int k = 0; k < BK; k++) {
            float af[TM], bf[TN];
#pragma unroll
            for (int i = 0; i < TM; i += 4) {
                float4 v = *reinterpret_cast<const float4*>(&As[k][ty * TM + i]);
                af[i + 0] = v.x; af[i + 1] = v.y; af[i + 2] = v.z; af[i + 3] = v.w;
            }
#pragma unroll
            for (int j = 0; j < TN; j += 4) {
                float4 v = *reinterpret_cast<const float4*>(&Bs[k][tx * TN + j]);
                bf[j + 0] = v.x; bf[j + 1] = v.y; bf[j + 2] = v.z; bf[j + 3] = v.w;
            }
#pragma unroll
            for (int i = 0; i < TM; i++)
#pragma unroll
                for (int j = 0; j < TN; j++)
                    acc[i][j] = fmaf(af[i], bf[j], acc[i][j]);
        }
        __syncthreads();
    }

    // epilogue
#pragma unroll
    for (int i = 0; i < TM; i++) {
        const int row = bm + ty * TM + i;
#pragma unroll
        for (int j = 0; j < TN; j++) {
            const int col = bn + tx * TN + j;
            float v = acc[i][j] + bias[col];
            if (epi == 1) {
                v = fmaxf(v, 0.f);
            } else if (epi == 2) {
                v += add[(size_t)row * addStride + col];
            }
            C[(size_t)row * N + col] = v;
        }
    }
}

// ---------------- LSTM pointwise step ----------------
__device__ __forceinline__ float sigmoidf_(float x) {
    return 1.f / (1.f + __expf(-x));
}

__global__ void lstm_pointwise(const float* __restrict__ gates,
                               float* __restrict__ h,
                               float* __restrict__ c,
                               float* __restrict__ hs_t)
{
    int idx = blockIdx.x * blockDim.x + threadIdx.x;
    if (idx >= B_ * H_) return;
    int b = idx / H_;
    int j = idx % H_;
    const float* g = gates + (size_t)b * G4;
    float iv = sigmoidf_(g[j]);
    float fv = sigmoidf_(g[j + H_]);
    float gv = tanhf(g[j + 2 * H_]);
    float ov = sigmoidf_(g[j + 3 * H_]);
    float cn = fv * c[idx] + iv * gv;
    float hn = ov * tanhf(cn);
    c[idx] = cn;
    h[idx] = hn;
    hs_t[idx] = hn;
}

__global__ void zero_hc(float* __restrict__ h, float* __restrict__ c)
{
    int idx = blockIdx.x * blockDim.x + threadIdx.x;
    if (idx < B_ * H_) { h[idx] = 0.f; c[idx] = 0.f; }
}

// ---------------- classifier: out[b*T+t][cc] = dot(hs[t][b], Wc[cc]) + bc ----------
__global__ void classifier_kernel(const float* __restrict__ hs,
                                  const float* __restrict__ Wc,
                                  const float* __restrict__ bc,
                                  float* __restrict__ out)
{
    __shared__ float sh[H_];
    const int bt = blockIdx.x;           // 0..B*T-1 (row of output)
    const int b = bt / T_;
    const int t = bt % T_;
    const float* hrow = hs + ((size_t)t * B_ + b) * H_;
    for (int i = threadIdx.x; i < H_; i += blockDim.x) sh[i] = hrow[i];
    __syncthreads();

    const int warp = threadIdx.x >> 5;
    const int lane = threadIdx.x & 31;
    const int nwarps = blockDim.x >> 5;
    for (int col = warp; col < C_; col += nwarps) {
        const float* w = Wc + (size_t)col * H_;
        float s = 0.f;
        for (int k = lane; k < H_; k += 32) s = fmaf(sh[k], w[k], s);
#pragma unroll
        for (int o = 16; o; o >>= 1) s += __shfl_xor_sync(0xffffffffu, s, o);
        if (lane == 0) out[(size_t)bt * C_ + col] = s + bc[col];
    }
}

// ---------------- launch ----------------
extern "C" void kernel_launch(void* const* d_in, const int* in_sizes, int n_in,
                              void* d_out, int out_size)
{
    (void)in_sizes; (void)n_in; (void)out_size;
    const float* x    = (const float*)d_in[0];  // [B,T,F]
    const float* W1   = (const float*)d_in[1];  // [N,F]
    const float* b1   = (const float*)d_in[2];  // [N]
    const float* W_ih = (const float*)d_in[3];  // [4H,N]
    const float* b_ih = (const float*)d_in[4];  // [4H]
    const float* W_hh = (const float*)d_in[5];  // [4H,H]
    const float* b_hh = (const float*)d_in[6];  // [4H]
    const float* Wc   = (const float*)d_in[7];  // [C,H]
    const float* bc   = (const float*)d_in[8];  // [C]
    float* out = (float*)d_out;

    float *z_p, *xg_p, *gates_p, *h_p, *c_p, *hs_p;
    cudaGetSymbolAddress((void**)&z_p,    g_z);
    cudaGetSymbolAddress((void**)&xg_p,   g_xg);
    cudaGetSymbolAddress((void**)&gates_p,g_gates);
    cudaGetSymbolAddress((void**)&h_p,    g_h);
    cudaGetSymbolAddress((void**)&c_p,    g_c);
    cudaGetSymbolAddress((void**)&hs_p,   g_hs);

    // 0) zero h, c
    zero_hc<<<(B_ * H_ + 255) / 256, 256>>>(h_p, c_p);

    // 1) z = relu(x @ W1^T + b1) : M=8192, N=1024, K=2048
    {
        dim3 grid(N_ / 128, (B_ * T_) / 128);
        gemm_nt<128, 128, 16, 8, 8><<<grid, 256>>>(
            x, W1, b1, nullptr, z_p, B_ * T_, N_, F_, /*epi=*/1, 0);
    }

    // 2) xg = z @ W_ih^T + b_ih : M=8192, N=4096, K=1024
    {
        dim3 grid(G4 / 128, (B_ * T_) / 128);
        gemm_nt<128, 128, 16, 8, 8><<<grid, 256>>>(
            z_p, W_ih, b_ih, nullptr, xg_p, B_ * T_, G4, N_, /*epi=*/0, 0);
    }

    // 3) recurrence: 64 steps
    for (int t = 0; t < T_; t++) {
        // gates = h @ W_hh^T + b_hh + xg[:,t,:]  : M=128, N=4096, K=1024
        dim3 grid(G4 / 32, B_ / 128);
        gemm_nt<128, 32, 16, 8, 4><<<grid, 128>>>(
            h_p, W_hh, b_hh, xg_p + (size_t)t * G4, gates_p,
            B_, G4, H_, /*epi=*/2, (long)T_ * G4);
        // pointwise cell update; hs[t] = h
        lstm_pointwise<<<(B_ * H_ + 255) / 256, 256>>>(
            gates_p, h_p, c_p, hs_p + (size_t)t * B_ * H_);
    }

    // 4) classifier: out[b*T+t][c] = hs[t][b] . Wc[c] + bc[c]
    classifier_kernel<<<B_ * T_, 256>>>(hs_p, Wc, bc, out);
}

// round 2
// speedup vs baseline: 2.8729x; 2.8729x over previous
#include <cuda_runtime.h>
#include <math.h>
#include <stdint.h>

// Problem constants
#define B_  128
#define T_  64
#define F_  2048
#define N_  1024
#define H_  1024
#define C_  22
#define G4  (4 * H_)   // 4096
#define NBLK 128       // persistent recurrence blocks

// ---------------- scratch (static device globals; no allocation) ----------------
__device__ float g_z [(size_t)B_ * T_ * N_];        // [8192, 1024]
__device__ float g_xg[(size_t)B_ * T_ * G4];        // [B, T, 4096]
__device__ float g_h [2][(size_t)B_ * H_];          // ping/pong hidden state
__device__ float g_hs[(size_t)T_ * B_ * H_];        // [T, B, H]
__device__ unsigned g_bar;                          // grid barrier counter

// ---------------- generic NT GEMM (for the two big input GEMMs) ----------------
// C[m,n] = sum_k A[m,k] * B[n,k]  (+bias, optional relu)
template <int BM, int BN, int BK, int TM, int TN>
__global__ void gemm_nt(const float* __restrict__ A,
                        const float* __restrict__ Bw,
                        const float* __restrict__ bias,
                        float* __restrict__ C,
                        int M, int N, int K, int relu)
{
    constexpr int NT = (BM / TM) * (BN / TN);
    __shared__ __align__(16) float As[BK][BM];
    __shared__ __align__(16) float Bs[BK][BN];

    const int tid = threadIdx.x;
    const int bm = blockIdx.y * BM;
    const int bn = blockIdx.x * BN;
    const int tx = tid % (BN / TN);
    const int ty = tid / (BN / TN);

    float acc[TM][TN];
#pragma unroll
    for (int i = 0; i < TM; i++)
#pragma unroll
        for (int j = 0; j < TN; j++) acc[i][j] = 0.f;

    for (int k0 = 0; k0 < K; k0 += BK) {
#pragma unroll
        for (int i = tid; i < BM * BK / 4; i += NT) {
            int row = i / (BK / 4);
            int kc  = (i % (BK / 4)) * 4;
            float4 v = *reinterpret_cast<const float4*>(
                &A[(size_t)(bm + row) * K + k0 + kc]);
            As[kc + 0][row] = v.x; As[kc + 1][row] = v.y;
            As[kc + 2][row] = v.z; As[kc + 3][row] = v.w;
        }
#pragma unroll
        for (int i = tid; i < BN * BK / 4; i += NT) {
            int row = i / (BK / 4);
            int kc  = (i % (BK / 4)) * 4;
            float4 v = *reinterpret_cast<const float4*>(
                &Bw[(size_t)(bn + row) * K + k0 + kc]);
            Bs[kc + 0][row] = v.x; Bs[kc + 1][row] = v.y;
            Bs[kc + 2][row] = v.z; Bs[kc + 3][row] = v.w;
        }
        __syncthreads();

#pragma unroll
        for (int k = 0; k < BK; k++) {
            float af[TM], bf[TN];
#pragma unroll
            for (int i = 0; i < TM; i += 4) {
                float4 v = *reinterpret_cast<const float4*>(&As[k][ty * TM + i]);
                af[i] = v.x; af[i+1] = v.y; af[i+2] = v.z; af[i+3] = v.w;
            }
#pragma unroll
            for (int j = 0; j < TN; j += 4) {
                float4 v = *reinterpret_cast<const float4*>(&Bs[k][tx * TN + j]);
                bf[j] = v.x; bf[j+1] = v.y; bf[j+2] = v.z; bf[j+3] = v.w;
            }
#pragma unroll
            for (int i = 0; i < TM; i++)
#pragma unroll
                for (int j = 0; j < TN; j++)
                    acc[i][j] = fmaf(af[i], bf[j], acc[i][j]);
        }
        __syncthreads();
    }

#pragma unroll
    for (int i = 0; i < TM; i++) {
        const int row = bm + ty * TM + i;
#pragma unroll
        for (int j = 0; j < TN; j++) {
            const int col = bn + tx * TN + j;
            float v = acc[i][j] + bias[col];
            if (relu) v = fmaxf(v, 0.f);
            C[(size_t)row * N + col] = v;
        }
    }
}

// ---------------- persistent LSTM recurrence (tf32 mma.sync) ----------------
// Grid: 128 blocks x 128 threads. Block `blk` owns hidden cols [blk*8, blk*8+8)
// i.e. gate columns {q*H + blk*8 + nn : q in 0..3, nn in 0..7} (32 cols).
// W_hh slice pre-arranged in smem as m16n8k8 tf32 B fragments (read once from DRAM).
// h staged via double-buffered cp.async; LSTM pointwise fused; c-state in registers.

__device__ __forceinline__ float sigmoidf_(float x) {
    return 1.f / (1.f + __expf(-x));
}
__device__ __forceinline__ float tf32r(float x) {
    uint32_t u;
    asm("cvt.rna.tf32.f32 %0, %1;" : "=r"(u) : "f"(x));
    return __uint_as_float(u);
}
__device__ __forceinline__ void mma_tf32(float* acc, float a0, float a1,
                                         float a2, float a3, float b0, float b1)
{
    asm volatile(
        "mma.sync.aligned.m16n8k8.row.col.f32.tf32.tf32.f32 "
        "{%0,%1,%2,%3},{%4,%5,%6,%7},{%8,%9},{%0,%1,%2,%3};"
        : "+f"(acc[0]), "+f"(acc[1]), "+f"(acc[2]), "+f"(acc[3])
        : "r"(__float_as_uint(a0)), "r"(__float_as_uint(a1)),
          "r"(__float_as_uint(a2)), "r"(__float_as_uint(a3)),
          "r"(__float_as_uint(b0)), "r"(__float_as_uint(b1)));
}

// htile stride 68 floats -> conflict-free A-fragment LDS
#define HT_STRIDE 68
#define WF_FLOATS 32768                // 128 k8 * 2 halves * 32 lanes * 4
#define SMEM_BYTES ((WF_FLOATS + 2 * 128 * HT_STRIDE) * 4)

__device__ __forceinline__ void stage_chunk(const float* __restrict__ hsrc,
                                            float* __restrict__ dst,
                                            int chunk, int tid)
{
    const int c4 = (tid & 15) * 4;     // 0..60
    const int rbase = tid >> 4;        // 0..7
    const float* src = hsrc + chunk * 64 + c4;
#pragma unroll
    for (int w = 0; w < 16; w++) {
        int row = rbase + w * 8;
        unsigned daddr = (unsigned)__cvta_generic_to_shared(dst + row * HT_STRIDE + c4);
        asm volatile("cp.async.cg.shared.global [%0], [%1], 16;\n"
                     :: "r"(daddr), "l"(src + (size_t)row * H_));
    }
}

__device__ __forceinline__ void grid_bar(int step) {
    __syncthreads();
    if (threadIdx.x == 0) {
        __threadfence();
        atomicAdd(&g_bar, 1u);
        const unsigned target = (unsigned)NBLK * (step + 1);
        unsigned v;
        do {
            asm volatile("ld.acquire.gpu.global.u32 %0, [%1];"
                         : "=r"(v) : "l"(&g_bar));
        } while (v < target);
    }
    __syncthreads();
}

__global__ void __launch_bounds__(128, 1)
lstm_persistent(const float* __restrict__ xg,
                const float* __restrict__ W_hh,
                const float* __restrict__ b_hh,
                float* __restrict__ hs)
{
    extern __shared__ float smem[];
    float* Wf = smem;                         // [k8][half][lane][4]
    float* ht = smem + WF_FLOATS;             // [2][128][HT_STRIDE]

    const int tid  = threadIdx.x;
    const int lane = tid & 31;
    const int warp = tid >> 5;
    const int blk  = blockIdx.x;
    const int grp  = lane >> 2;   // 0..7
    const int tig  = lane & 3;    // 0..3
    const int row0 = warp * 32;   // warp's 32 batch rows

    // ---- one-time: load W_hh slice as tf32 B fragments ----
    for (int idx = tid; idx < WF_FLOATS; idx += 128) {
        int slot = idx & 3;
        int ln   = (idx >> 2) & 31;
        int half = (idx >> 7) & 1;
        int k8   = idx >> 8;
        int n    = half * 2 + (slot >> 1);
        int bsel = slot & 1;
        int k    = k8 * 8 + (ln & 3) + bsel * 4;
        int nn   = ln >> 2;
        int gcol = n * H_ + blk * 8 + nn;
        Wf[idx] = tf32r(W_hh[(size_t)gcol * H_ + k]);
    }

    // b_hh for this thread's output cols (col = 2*tig + cc), per gate n
    float bh[8];
#pragma unroll
    for (int n = 0; n < 4; n++) {
        int gc = n * H_ + blk * 8 + 2 * tig;
        bh[2 * n]     = b_hh[gc];
        bh[2 * n + 1] = b_hh[gc + 1];
    }

    float cst[8];   // c-state: [mt(2)][rh(2)][cc(2)]
#pragma unroll
    for (int i = 0; i < 8; i++) cst[i] = 0.f;

    __syncthreads();

    for (int t = 0; t < T_; t++) {
        const float* hin  = g_h[t & 1];
        float*       hout = g_h[(t + 1) & 1];

        // prefetch xg addends for this step (32 values)
        float xgv[32];
#pragma unroll
        for (int mt = 0; mt < 2; mt++)
#pragma unroll
        for (int n = 0; n < 4; n++)
#pragma unroll
        for (int rh = 0; rh < 2; rh++) {
            int row = row0 + mt * 16 + grp + rh * 8;      // batch index
            size_t base = ((size_t)row * T_ + t) * G4 + n * H_ + blk * 8 + 2 * tig;
            float2 v = *reinterpret_cast<const float2*>(&xg[base]);
            int o = ((mt * 4 + n) * 2 + rh) * 2;
            xgv[o] = v.x; xgv[o + 1] = v.y;
        }

        float acc[2][4][4];
#pragma unroll
        for (int mt = 0; mt < 2; mt++)
#pragma unroll
        for (int n = 0; n < 4; n++)
#pragma unroll
        for (int c = 0; c < 4; c++) acc[mt][n][c] = 0.f;

        // stage first chunk
        stage_chunk(hin, ht, 0, tid);
        asm volatile("cp.async.commit_group;\n");

        for (int chunk = 0; chunk < 16; chunk++) {
            if (chunk + 1 < 16) {
                stage_chunk(hin, ht + ((chunk + 1) & 1) * 128 * HT_STRIDE,
                            chunk + 1, tid);
                asm volatile("cp.async.commit_group;\n");
                asm volatile("cp.async.wait_group 1;\n");
            } else {
                asm volatile("cp.async.wait_group 0;\n");
            }
            __syncthreads();

            const float* hb = ht + (chunk & 1) * 128 * HT_STRIDE;
#pragma unroll
            for (int j = 0; j < 8; j++) {
                int k8 = chunk * 8 + j;
                float4 b0 = *reinterpret_cast<const float4*>(
                    &Wf[((k8 * 2 + 0) * 32 + lane) * 4]);
                float4 b1 = *reinterpret_cast<const float4*>(
                    &Wf[((k8 * 2 + 1) * 32 + lane) * 4]);
#pragma unroll
                for (int mt = 0; mt < 2; mt++) {
                    int r = row0 + mt * 16 + grp;
                    float a0 = hb[r * HT_STRIDE + j * 8 + tig];
                    float a1 = hb[(r + 8) * HT_STRIDE + j * 8 + tig];
                    float a2 = hb[r * HT_STRIDE + j * 8 + tig + 4];
                    float a3 = hb[(r + 8) * HT_STRIDE + j * 8 + tig + 4];
                    mma_tf32(acc[mt][0], a0, a1, a2, a3, b0.x, b0.y);
                    mma_tf32(acc[mt][1], a0, a1, a2, a3, b0.z, b0.w);
                    mma_tf32(acc[mt][2], a0, a1, a2, a3, b1.x, b1.y);
                    mma_tf32(acc[mt][3], a0, a1, a2, a3, b1.z, b1.w);
                }
            }
            __syncthreads();
        }

        // fused LSTM pointwise (c-state in regs), write h (tf32-rounded) + hs
#pragma unroll
        for (int mt = 0; mt < 2; mt++)
#pragma unroll
        for (int rh = 0; rh < 2; rh++) {
            int row = row0 + mt * 16 + grp + rh * 8;
            int hc  = blk * 8 + 2 * tig;
            float hpair[2];
#pragma unroll
            for (int cc = 0; cc < 2; cc++) {
                int ci = rh * 2 + cc;
                float gi = acc[mt][0][ci] + xgv[((mt*4+0)*2+rh)*2+cc] + bh[0+cc];
                float gf = acc[mt][1][ci] + xgv[((mt*4+1)*2+rh)*2+cc] + bh[2+cc];
                float gg = acc[mt][2][ci] + xgv[((mt*4+2)*2+rh)*2+cc] + bh[4+cc];
                float go = acc[mt][3][ci] + xgv[((mt*4+3)*2+rh)*2+cc] + bh[6+cc];
                float iv = sigmoidf_(gi);
                float fv = sigmoidf_(gf);
                float gv = tanhf(gg);
                float ov = sigmoidf_(go);
                int csi = mt * 4 + rh * 2 + cc;
                float cn = fv * cst[csi] + iv * gv;
                cst[csi] = cn;
                hpair[cc] = tf32r(ov * tanhf(cn));
            }
            *reinterpret_cast<float2*>(&hout[(size_t)row * H_ + hc]) =
                make_float2(hpair[0], hpair[1]);
            *reinterpret_cast<float2*>(&hs[((size_t)t * B_ + row) * H_ + hc]) =
                make_float2(hpair[0], hpair[1]);
        }

        if (t < T_ - 1) grid_bar(t);
    }
}

// ---------------- classifier ----------------
__global__ void classifier_kernel(const float* __restrict__ hs,
                                  const float* __restrict__ Wc,
                                  const float* __restrict__ bc,
                                  float* __restrict__ out)
{
    __shared__ float sh[H_];
    const int bt = blockIdx.x;
    const int b = bt / T_;
    const int t = bt % T_;
    const float* hrow = hs + ((size_t)t * B_ + b) * H_;
    for (int i = threadIdx.x; i < H_; i += blockDim.x) sh[i] = hrow[i];
    __syncthreads();

    const int warp = threadIdx.x >> 5;
    const int lane = threadIdx.x & 31;
    const int nwarps = blockDim.x >> 5;
    for (int col = warp; col < C_; col += nwarps) {
        const float* w = Wc + (size_t)col * H_;
        float s = 0.f;
        for (int k = lane; k < H_; k += 32) s = fmaf(sh[k], w[k], s);
#pragma unroll
        for (int o = 16; o; o >>= 1) s += __shfl_xor_sync(0xffffffffu, s, o);
        if (lane == 0) out[(size_t)bt * C_ + col] = s + bc[col];
    }
}

// ---------------- launch ----------------
extern "C" void kernel_launch(void* const* d_in, const int* in_sizes, int n_in,
                              void* d_out, int out_size)
{
    (void)in_sizes; (void)n_in; (void)out_size;
    const float* x    = (const float*)d_in[0];
    const float* W1   = (const float*)d_in[1];
    const float* b1   = (const float*)d_in[2];
    const float* W_ih = (const float*)d_in[3];
    const float* b_ih = (const float*)d_in[4];
    const float* W_hh = (const float*)d_in[5];
    const float* b_hh = (const float*)d_in[6];
    const float* Wc   = (const float*)d_in[7];
    const float* bc   = (const float*)d_in[8];
    float* out = (float*)d_out;

    float *z_p, *xg_p, *h_p, *hs_p; unsigned* bar_p;
    cudaGetSymbolAddress((void**)&z_p,  g_z);
    cudaGetSymbolAddress((void**)&xg_p, g_xg);
    cudaGetSymbolAddress((void**)&h_p,  g_h);
    cudaGetSymbolAddress((void**)&hs_p, g_hs);
    cudaGetSymbolAddress((void**)&bar_p, g_bar);

    // reset barrier counter + zero initial h (ping buffer)
    cudaMemsetAsync(bar_p, 0, sizeof(unsigned));
    cudaMemsetAsync(h_p, 0, (size_t)B_ * H_ * sizeof(float));

    // 1) z = relu(x @ W1^T + b1)
    {
        dim3 grid(N_ / 128, (B_ * T_) / 128);
        gemm_nt<128, 128, 16, 8, 8><<<grid, 256>>>(
            x, W1, b1, z_p, B_ * T_, N_, F_, 1);
    }
    // 2) xg = z @ W_ih^T + b_ih
    {
        dim3 grid(G4 / 128, (B_ * T_) / 128);
        gemm_nt<128, 128, 16, 8, 8><<<grid, 256>>>(
            z_p, W_ih, b_ih, xg_p, B_ * T_, G4, N_, 0);
    }
    // 3) persistent recurrence (tensor cores, one kernel for all 64 steps)
    cudaFuncSetAttribute(lstm_persistent,
                         cudaFuncAttributeMaxDynamicSharedMemorySize, SMEM_BYTES);
    lstm_persistent<<<NBLK, 128, SMEM_BYTES>>>(xg_p, W_hh, b_hh, hs_p);

    // 4) classifier
    classifier_kernel<<<B_ * T_, 256>>>(hs_p, Wc, bc, out);
}

// round 3
// speedup vs baseline: 5.6618x; 1.9707x over previous
#include <cuda_runtime.h>
#include <math.h>
#include <stdint.h>

// Problem constants
#define B_  128
#define T_  64
#define F_  2048
#define N_  1024
#define H_  1024
#define C_  22
#define G4  (4 * H_)   // 4096
#define NBLK 128       // persistent recurrence blocks

// ---------------- scratch (static device globals; no allocation) ----------------
__device__ float g_z  [(size_t)B_ * T_ * N_];       // [8192, 1024] (tf32-rounded)
__device__ float g_xg [(size_t)B_ * T_ * G4];       // [B, T, 4096]
__device__ float g_h  [2][(size_t)B_ * H_];         // ping/pong hidden state
__device__ float g_hs [(size_t)T_ * B_ * H_];       // [T, B, H]
__device__ float g_xr [(size_t)B_ * T_ * F_];       // tf32-rounded x
__device__ float g_w1r[(size_t)N_ * F_];            // tf32-rounded W1
__device__ float g_wir[(size_t)G4 * N_];            // tf32-rounded W_ih
__device__ unsigned g_bar;                          // grid barrier counter

__device__ __forceinline__ float sigmoidf_(float x) {
    return 1.f / (1.f + __expf(-x));
}
__device__ __forceinline__ float tf32r(float x) {
    uint32_t u;
    asm("cvt.rna.tf32.f32 %0, %1;" : "=r"(u) : "f"(x));
    return __uint_as_float(u);
}
__device__ __forceinline__ void mma_tf32(float* acc, float a0, float a1,
                                         float a2, float a3, float b0, float b1)
{
    asm volatile(
        "mma.sync.aligned.m16n8k8.row.col.f32.tf32.tf32.f32 "
        "{%0,%1,%2,%3},{%4,%5,%6,%7},{%8,%9},{%0,%1,%2,%3};"
        : "+f"(acc[0]), "+f"(acc[1]), "+f"(acc[2]), "+f"(acc[3])
        : "r"(__float_as_uint(a0)), "r"(__float_as_uint(a1)),
          "r"(__float_as_uint(a2)), "r"(__float_as_uint(a3)),
          "r"(__float_as_uint(b0)), "r"(__float_as_uint(b1)));
}

// ---------------- tf32 pre-round copy ----------------
__global__ void round_tf32_copy(const float4* __restrict__ in,
                                float4* __restrict__ out, int n4)
{
    int i = blockIdx.x * blockDim.x + threadIdx.x;
    if (i >= n4) return;
    float4 v = in[i];
    v.x = tf32r(v.x); v.y = tf32r(v.y); v.z = tf32r(v.z); v.w = tf32r(v.w);
    out[i] = v;
}

// ---------------- tensor-core NT GEMM (tf32 mma.sync) ----------------
// C[m,n] = sum_k A[m,k]*B[n,k] (+bias), epi: 0=none, 1=relu+tf32round
// A, B must be pre-rounded to tf32. BM=BN=128, BK=32, 256 threads (8 warps 2x4).
#define GPAD 36
#define GSA (128 * GPAD)
#define GEMM_SMEM (4 * GSA * 4)   // 2 bufs * (A+B) * 128*36 floats = 73728 B

__global__ void __launch_bounds__(256)
gemm_tf32(const float* __restrict__ A, const float* __restrict__ Bw,
          const float* __restrict__ bias, float* __restrict__ C,
          int M, int N, int K, int epi)
{
    extern __shared__ float sm[];
    float* As = sm;            // [2][128][36]
    float* Bs = sm + 2 * GSA;  // [2][128][36]

    const int tid = threadIdx.x;
    const int lane = tid & 31, warp = tid >> 5;
    const int bm = blockIdx.y * 128, bn = blockIdx.x * 128;
    const int wm = (warp & 1) * 64, wn = (warp >> 1) * 32;
    const int grp = lane >> 2, tig = lane & 3;

    float acc[4][4][4];
#pragma unroll
    for (int a = 0; a < 4; a++)
#pragma unroll
        for (int b = 0; b < 4; b++)
#pragma unroll
            for (int c = 0; c < 4; c++) acc[a][b][c] = 0.f;

    auto load_tiles = [&](int k0, int buf) {
#pragma unroll
        for (int i = tid; i < 128 * 8; i += 256) {
            int r = i >> 3, c4 = (i & 7) * 4;
            unsigned da = (unsigned)__cvta_generic_to_shared(
                &As[buf * GSA + r * GPAD + c4]);
            asm volatile("cp.async.cg.shared.global [%0], [%1], 16;\n"
                         :: "r"(da), "l"(&A[(size_t)(bm + r) * K + k0 + c4]));
        }
#pragma unroll
        for (int i = tid; i < 128 * 8; i += 256) {
            int r = i >> 3, c4 = (i & 7) * 4;
            unsigned da = (unsigned)__cvta_generic_to_shared(
                &Bs[buf * GSA + r * GPAD + c4]);
            asm volatile("cp.async.cg.shared.global [%0], [%1], 16;\n"
                         :: "r"(da), "l"(&Bw[(size_t)(bn + r) * K + k0 + c4]));
        }
        asm volatile("cp.async.commit_group;\n");
    };

    load_tiles(0, 0);
    const int nk = K / 32;
    for (int kb = 0; kb < nk; kb++) {
        if (kb + 1 < nk) {
            load_tiles((kb + 1) * 32, (kb + 1) & 1);
            asm volatile("cp.async.wait_group 1;\n");
        } else {
            asm volatile("cp.async.wait_group 0;\n");
        }
        __syncthreads();

        const float* a_s = As + (kb & 1) * GSA;
        const float* b_s = Bs + (kb & 1) * GSA;
#pragma unroll
        for (int k8 = 0; k8 < 4; k8++) {
            const int k = k8 * 8;
            float af[4][4], bf[4][2];
#pragma unroll
            for (int mt = 0; mt < 4; mt++) {
                int r = wm + mt * 16 + grp;
                af[mt][0] = a_s[r * GPAD + k + tig];
                af[mt][1] = a_s[(r + 8) * GPAD + k + tig];
                af[mt][2] = a_s[r * GPAD + k + tig + 4];
                af[mt][3] = a_s[(r + 8) * GPAD + k + tig + 4];
            }
#pragma unroll
            for (int nt = 0; nt < 4; nt++) {
                int n = wn + nt * 8 + grp;
                bf[nt][0] = b_s[n * GPAD + k + tig];
                bf[nt][1] = b_s[n * GPAD + k + tig + 4];
            }
#pragma unroll
            for (int mt = 0; mt < 4; mt++)
#pragma unroll
                for (int nt = 0; nt < 4; nt++)
                    mma_tf32(acc[mt][nt], af[mt][0], af[mt][1], af[mt][2],
                             af[mt][3], bf[nt][0], bf[nt][1]);
        }
        __syncthreads();
    }

    // epilogue
#pragma unroll
    for (int mt = 0; mt < 4; mt++) {
#pragma unroll
        for (int rh = 0; rh < 2; rh++) {
            int row = bm + wm + mt * 16 + grp + rh * 8;
#pragma unroll
            for (int nt = 0; nt < 4; nt++) {
                int col = bn + wn + nt * 8 + tig * 2;
                float v0 = acc[mt][nt][rh * 2 + 0] + bias[col];
                float v1 = acc[mt][nt][rh * 2 + 1] + bias[col + 1];
                if (epi == 1) {
                    v0 = tf32r(fmaxf(v0, 0.f));
                    v1 = tf32r(fmaxf(v1, 0.f));
                }
                *reinterpret_cast<float2*>(&C[(size_t)row * N + col]) =
                    make_float2(v0, v1);
            }
        }
    }
}

// ---------------- persistent LSTM recurrence (tf32 mma.sync) ----------------
#define HT_STRIDE 68
#define WF_FLOATS 32768
#define SMEM_BYTES ((WF_FLOATS + 2 * 128 * HT_STRIDE) * 4)

__device__ __forceinline__ void stage_chunk(const float* __restrict__ hsrc,
                                            float* __restrict__ dst,
                                            int chunk, int tid)
{
    const int c4 = (tid & 15) * 4;
    const int rbase = tid >> 4;
    const float* src = hsrc + chunk * 64 + c4;
#pragma unroll
    for (int w = 0; w < 16; w++) {
        int row = rbase + w * 8;
        unsigned daddr = (unsigned)__cvta_generic_to_shared(dst + row * HT_STRIDE + c4);
        asm volatile("cp.async.cg.shared.global [%0], [%1], 16;\n"
                     :: "r"(daddr), "l"(src + (size_t)row * H_));
    }
}

__device__ __forceinline__ void grid_bar(int step) {
    __syncthreads();
    if (threadIdx.x == 0) {
        __threadfence();
        atomicAdd(&g_bar, 1u);
        const unsigned target = (unsigned)NBLK * (step + 1);
        unsigned v;
        do {
            asm volatile("ld.acquire.gpu.global.u32 %0, [%1];"
                         : "=r"(v) : "l"(&g_bar));
        } while (v < target);
    }
    __syncthreads();
}

__global__ void __launch_bounds__(128, 1)
lstm_persistent(const float* __restrict__ xg,
                const float* __restrict__ W_hh,
                const float* __restrict__ b_hh,
                float* __restrict__ hs)
{
    extern __shared__ float smem[];
    float* Wf = smem;
    float* ht = smem + WF_FLOATS;

    const int tid  = threadIdx.x;
    const int lane = tid & 31;
    const int warp = tid >> 5;
    const int blk  = blockIdx.x;
    const int grp  = lane >> 2;
    const int tig  = lane & 3;
    const int row0 = warp * 32;

    for (int idx = tid; idx < WF_FLOATS; idx += 128) {
        int slot = idx & 3;
        int ln   = (idx >> 2) & 31;
        int half = (idx >> 7) & 1;
        int k8   = idx >> 8;
        int n    = half * 2 + (slot >> 1);
        int bsel = slot & 1;
        int k    = k8 * 8 + (ln & 3) + bsel * 4;
        int nn   = ln >> 2;
        int gcol = n * H_ + blk * 8 + nn;
        Wf[idx] = tf32r(W_hh[(size_t)gcol * H_ + k]);
    }

    float bh[8];
#pragma unroll
    for (int n = 0; n < 4; n++) {
        int gc = n * H_ + blk * 8 + 2 * tig;
        bh[2 * n]     = b_hh[gc];
        bh[2 * n + 1] = b_hh[gc + 1];
    }

    float cst[8];
#pragma unroll
    for (int i = 0; i < 8; i++) cst[i] = 0.f;

    __syncthreads();

    for (int t = 0; t < T_; t++) {
        const float* hin  = g_h[t & 1];
        float*       hout = g_h[(t + 1) & 1];

        float xgv[32];
#pragma unroll
        for (int mt = 0; mt < 2; mt++)
#pragma unroll
        for (int n = 0; n < 4; n++)
#pragma unroll
        for (int rh = 0; rh < 2; rh++) {
            int row = row0 + mt * 16 + grp + rh * 8;
            size_t base = ((size_t)row * T_ + t) * G4 + n * H_ + blk * 8 + 2 * tig;
            float2 v = *reinterpret_cast<const float2*>(&xg[base]);
            int o = ((mt * 4 + n) * 2 + rh) * 2;
            xgv[o] = v.x; xgv[o + 1] = v.y;
        }

        float acc[2][4][4];
#pragma unroll
        for (int mt = 0; mt < 2; mt++)
#pragma unroll
        for (int n = 0; n < 4; n++)
#pragma unroll
        for (int c = 0; c < 4; c++) acc[mt][n][c] = 0.f;

        stage_chunk(hin, ht, 0, tid);
        asm volatile("cp.async.commit_group;\n");

        for (int chunk = 0; chunk < 16; chunk++) {
            if (chunk + 1 < 16) {
                stage_chunk(hin, ht + ((chunk + 1) & 1) * 128 * HT_STRIDE,
                            chunk + 1, tid);
                asm volatile("cp.async.commit_group;\n");
                asm volatile("cp.async.wait_group 1;\n");
            } else {
                asm volatile("cp.async.wait_group 0;\n");
            }
            __syncthreads();

            const float* hb = ht + (chunk & 1) * 128 * HT_STRIDE;
#pragma unroll
            for (int j = 0; j < 8; j++) {
                int k8 = chunk * 8 + j;
                float4 b0 = *reinterpret_cast<const float4*>(
                    &Wf[((k8 * 2 + 0) * 32 + lane) * 4]);
                float4 b1 = *reinterpret_cast<const float4*>(
                    &Wf[((k8 * 2 + 1) * 32 + lane) * 4]);
#pragma unroll
                for (int mt = 0; mt < 2; mt++) {
                    int r = row0 + mt * 16 + grp;
                    float a0 = hb[r * HT_STRIDE + j * 8 + tig];
                    float a1 = hb[(r + 8) * HT_STRIDE + j * 8 + tig];
                    float a2 = hb[r * HT_STRIDE + j * 8 + tig + 4];
                    float a3 = hb[(r + 8) * HT_STRIDE + j * 8 + tig + 4];
                    mma_tf32(acc[mt][0], a0, a1, a2, a3, b0.x, b0.y);
                    mma_tf32(acc[mt][1], a0, a1, a2, a3, b0.z, b0.w);
                    mma_tf32(acc[mt][2], a0, a1, a2, a3, b1.x, b1.y);
                    mma_tf32(acc[mt][3], a0, a1, a2, a3, b1.z, b1.w);
                }
            }
            __syncthreads();
        }

#pragma unroll
        for (int mt = 0; mt < 2; mt++)
#pragma unroll
        for (int rh = 0; rh < 2; rh++) {
            int row = row0 + mt * 16 + grp + rh * 8;
            int hc  = blk * 8 + 2 * tig;
            float hpair[2];
#pragma unroll
            for (int cc = 0; cc < 2; cc++) {
                int ci = rh * 2 + cc;
                float gi = acc[mt][0][ci] + xgv[((mt*4+0)*2+rh)*2+cc] + bh[0+cc];
                float gf = acc[mt][1][ci] + xgv[((mt*4+1)*2+rh)*2+cc] + bh[2+cc];
                float gg = acc[mt][2][ci] + xgv[((mt*4+2)*2+rh)*2+cc] + bh[4+cc];
                float go = acc[mt][3][ci] + xgv[((mt*4+3)*2+rh)*2+cc] + bh[6+cc];
                float iv = sigmoidf_(gi);
                float fv = sigmoidf_(gf);
                float gv = tanhf(gg);
                float ov = sigmoidf_(go);
                int csi = mt * 4 + rh * 2 + cc;
                float cn = fv * cst[csi] + iv * gv;
                cst[csi] = cn;
                hpair[cc] = tf32r(ov * tanhf(cn));
            }
            *reinterpret_cast<float2*>(&hout[(size_t)row * H_ + hc]) =
                make_float2(hpair[0], hpair[1]);
            *reinterpret_cast<float2*>(&hs[((size_t)t * B_ + row) * H_ + hc]) =
                make_float2(hpair[0], hpair[1]);
        }

        if (t < T_ - 1) grid_bar(t);
    }
}

// ---------------- classifier ----------------
__global__ void classifier_kernel(const float* __restrict__ hs,
                                  const float* __restrict__ Wc,
                                  const float* __restrict__ bc,
                                  float* __restrict__ out)
{
    __shared__ float sh[H_];
    const int bt = blockIdx.x;
    const int b = bt / T_;
    const int t = bt % T_;
    const float* hrow = hs + ((size_t)t * B_ + b) * H_;
    for (int i = threadIdx.x; i < H_; i += blockDim.x) sh[i] = hrow[i];
    __syncthreads();

    const int warp = threadIdx.x >> 5;
    const int lane = threadIdx.x & 31;
    const int nwarps = blockDim.x >> 5;
    for (int col = warp; col < C_; col += nwarps) {
        const float* w = Wc + (size_t)col * H_;
        float s = 0.f;
        for (int k = lane; k < H_; k += 32) s = fmaf(sh[k], w[k], s);
#pragma unroll
        for (int o = 16; o; o >>= 1) s += __shfl_xor_sync(0xffffffffu, s, o);
        if (lane == 0) out[(size_t)bt * C_ + col] = s + bc[col];
    }
}

// ---------------- launch ----------------
extern "C" void kernel_launch(void* const* d_in, const int* in_sizes, int n_in,
                              void* d_out, int out_size)
{
    (void)in_sizes; (void)n_in; (void)out_size;
    const float* x    = (const float*)d_in[0];
    const float* W1   = (const float*)d_in[1];
    const float* b1   = (const float*)d_in[2];
    const float* W_ih = (const float*)d_in[3];
    const float* b_ih = (const float*)d_in[4];
    const float* W_hh = (const float*)d_in[5];
    const float* b_hh = (const float*)d_in[6];
    const float* Wc   = (const float*)d_in[7];
    const float* bc   = (const float*)d_in[8];
    float* out = (float*)d_out;

    float *z_p, *xg_p, *h_p, *hs_p, *xr_p, *w1r_p, *wir_p; unsigned* bar_p;
    cudaGetSymbolAddress((void**)&z_p,   g_z);
    cudaGetSymbolAddress((void**)&xg_p,  g_xg);
    cudaGetSymbolAddress((void**)&h_p,   g_h);
    cudaGetSymbolAddress((void**)&hs_p,  g_hs);
    cudaGetSymbolAddress((void**)&xr_p,  g_xr);
    cudaGetSymbolAddress((void**)&w1r_p, g_w1r);
    cudaGetSymbolAddress((void**)&wir_p, g_wir);
    cudaGetSymbolAddress((void**)&bar_p, g_bar);

    cudaMemsetAsync(bar_p, 0, sizeof(unsigned));
    cudaMemsetAsync(h_p, 0, (size_t)B_ * H_ * sizeof(float));

    // 0) pre-round inputs to tf32
    {
        int n4 = B_ * T_ * F_ / 4;
        round_tf32_copy<<<(n4 + 255) / 256, 256>>>((const float4*)x,
                                                   (float4*)xr_p, n4);
        n4 = N_ * F_ / 4;
        round_tf32_copy<<<(n4 + 255) / 256, 256>>>((const float4*)W1,
                                                   (float4*)w1r_p, n4);
        n4 = G4 * N_ / 4;
        round_tf32_copy<<<(n4 + 255) / 256, 256>>>((const float4*)W_ih,
                                                   (float4*)wir_p, n4);
    }

    cudaFuncSetAttribute(gemm_tf32,
                         cudaFuncAttributeMaxDynamicSharedMemorySize, GEMM_SMEM);

    // 1) z = tf32round(relu(x @ W1^T + b1))
    {
        dim3 grid(N_ / 128, (B_ * T_) / 128);
        gemm_tf32<<<grid, 256, GEMM_SMEM>>>(xr_p, w1r_p, b1, z_p,
                                            B_ * T_, N_, F_, 1);
    }
    // 2) xg = z @ W_ih^T + b_ih
    {
        dim3 grid(G4 / 128, (B_ * T_) / 128);
        gemm_tf32<<<grid, 256, GEMM_SMEM>>>(z_p, wir_p, b_ih, xg_p,
                                            B_ * T_, G4, N_, 0);
    }
    // 3) persistent recurrence
    cudaFuncSetAttribute(lstm_persistent,
                         cudaFuncAttributeMaxDynamicSharedMemorySize, SMEM_BYTES);
    lstm_persistent<<<NBLK, 128, SMEM_BYTES>>>(xg_p, W_hh, b_hh, hs_p);

    // 4) classifier
    classifier_kernel<<<B_ * T_, 256>>>(hs_p, Wc, bc, out);
}

// round 5
// speedup vs baseline: 8.7445x; 1.5445x over previous
#include <cuda_runtime.h>
#include <cuda_fp16.h>
#include <math.h>
#include <stdint.h>

// Problem constants
#define B_  128
#define T_  64
#define F_  2048
#define N_  1024
#define H_  1024
#define C_  22
#define G4  (4 * H_)   // 4096
#define NBLK 128       // persistent recurrence blocks

// ---------------- scratch (static device globals; no allocation) ----------------
__device__ __half g_z  [(size_t)B_ * T_ * N_];      // [8192, 1024] fp16
__device__ float  g_xg [(size_t)B_ * T_ * G4];      // [B, T, 4096] fp32
__device__ __half g_h  [2][(size_t)B_ * H_];        // ping/pong hidden (fp16)
__device__ float  g_hs [(size_t)T_ * B_ * H_];      // [T, B, H] fp32
__device__ __half g_xh [(size_t)B_ * T_ * F_];      // fp16 x
__device__ __half g_w1h[(size_t)N_ * F_];           // fp16 W1
__device__ __half g_wih[(size_t)G4 * N_];           // fp16 W_ih
__device__ unsigned g_bar;                          // grid barrier counter

__device__ __forceinline__ float sigmoidf_(float x) {
    return 1.f / (1.f + __expf(-x));
}
__device__ __forceinline__ uint32_t packh2(float a, float b) {
    __half2 h = __floats2half2_rn(a, b);
    return *reinterpret_cast<uint32_t*>(&h);
}
__device__ __forceinline__ void mma_f16(float* acc, uint32_t a0, uint32_t a1,
                                        uint32_t a2, uint32_t a3,
                                        uint32_t b0, uint32_t b1)
{
    asm volatile(
        "mma.sync.aligned.m16n8k16.row.col.f32.f16.f16.f32 "
        "{%0,%1,%2,%3},{%4,%5,%6,%7},{%8,%9},{%0,%1,%2,%3};"
        : "+f"(acc[0]), "+f"(acc[1]), "+f"(acc[2]), "+f"(acc[3])
        : "r"(a0), "r"(a1), "r"(a2), "r"(a3), "r"(b0), "r"(b1));
}

// ---------------- fp32 -> fp16 convert ----------------
__global__ void to_half(const float4* __restrict__ in,
                        __half2* __restrict__ out, int n4)
{
    int i = blockIdx.x * blockDim.x + threadIdx.x;
    if (i >= n4) return;
    float4 v = in[i];
    out[2 * i]     = __floats2half2_rn(v.x, v.y);
    out[2 * i + 1] = __floats2half2_rn(v.z, v.w);
}

// ============================================================================
// fp16 NT GEMM (mma.sync m16n8k16): C[m,n] = sum_k A[m,k]*B[n,k] (+bias)
// BM=BN=128, BK=64 halfs, 256 threads (8 warps 2x4), 3-stage cp.async
// epi: 0 = +bias, write fp32 ; 1 = relu(+bias), write fp16
// ============================================================================
#define GBK 64
#define GSTR 72                       // halfs per smem row (144 B, bank-free)
#define GST_BYTES (128 * GSTR * 2)    // 18432 per matrix per stage
#define GSTAGE_BYTES (2 * GST_BYTES)  // 36864
#define GSTAGES 3
#define GEMM_SMEM (GSTAGES * GSTAGE_BYTES)  // 110592

__global__ void __launch_bounds__(256)
gemm_h(const __half* __restrict__ A, const __half* __restrict__ Bw,
       const float* __restrict__ bias, void* __restrict__ Cout,
       int Ntot, int K, int epi)
{
    extern __shared__ __align__(16) char gsm[];

    const int tid = threadIdx.x;
    const int lane = tid & 31, warp = tid >> 5;
    const int bm = blockIdx.y * 128, bn = blockIdx.x * 128;
    const int wm = (warp & 1) * 64, wn = (warp >> 1) * 32;
    const int grp = lane >> 2, tig = lane & 3;
    const int nk = K / GBK;

    float acc[4][4][4];
#pragma unroll
    for (int a = 0; a < 4; a++)
#pragma unroll
        for (int b = 0; b < 4; b++)
#pragma unroll
            for (int c = 0; c < 4; c++) acc[a][b][c] = 0.f;

    auto load_stage = [&](int kb, int buf) {
        const int k0 = kb * GBK;
        char* as = gsm + buf * GSTAGE_BYTES;
        char* bs = as + GST_BYTES;
        const int r = tid >> 3, p = tid & 7;   // 128 rows, 8x16B pieces
#pragma unroll
        for (int w = 0; w < 4; w++) {
            int row = r + w * 32;
            unsigned da = (unsigned)__cvta_generic_to_shared(
                as + (row * GSTR + p * 8) * 2);
            asm volatile("cp.async.cg.shared.global [%0], [%1], 16;\n"
                         :: "r"(da), "l"(&A[(size_t)(bm + row) * K + k0 + p * 8]));
            unsigned db = (unsigned)__cvta_generic_to_shared(
                bs + (row * GSTR + p * 8) * 2);
            asm volatile("cp.async.cg.shared.global [%0], [%1], 16;\n"
                         :: "r"(db), "l"(&Bw[(size_t)(bn + row) * K + k0 + p * 8]));
        }
        asm volatile("cp.async.commit_group;\n");
    };

    load_stage(0, 0);
    if (nk > 1) load_stage(1, 1);

    for (int kb = 0; kb < nk; kb++) {
        if (kb == nk - 1) asm volatile("cp.async.wait_group 0;\n");
        else              asm volatile("cp.async.wait_group 1;\n");
        __syncthreads();

        const __half* a_s = (const __half*)(gsm + (kb % GSTAGES) * GSTAGE_BYTES);
        const __half* b_s = (const __half*)((const char*)a_s + GST_BYTES);
#pragma unroll
        for (int s = 0; s < 4; s++) {
            const int koff = s * 16 + 2 * tig;
            uint32_t af[4][4], bf[4][2];
#pragma unroll
            for (int mt = 0; mt < 4; mt++) {
                int r = wm + mt * 16 + grp;
                af[mt][0] = *(const uint32_t*)&a_s[r * GSTR + koff];
                af[mt][1] = *(const uint32_t*)&a_s[(r + 8) * GSTR + koff];
                af[mt][2] = *(const uint32_t*)&a_s[r * GSTR + koff + 8];
                af[mt][3] = *(const uint32_t*)&a_s[(r + 8) * GSTR + koff + 8];
            }
#pragma unroll
            for (int nt = 0; nt < 4; nt++) {
                int n = wn + nt * 8 + grp;
                bf[nt][0] = *(const uint32_t*)&b_s[n * GSTR + koff];
                bf[nt][1] = *(const uint32_t*)&b_s[n * GSTR + koff + 8];
            }
#pragma unroll
            for (int mt = 0; mt < 4; mt++)
#pragma unroll
                for (int nt = 0; nt < 4; nt++)
                    mma_f16(acc[mt][nt], af[mt][0], af[mt][1], af[mt][2],
                            af[mt][3], bf[nt][0], bf[nt][1]);
        }
        __syncthreads();
        if (kb + 2 < nk) load_stage(kb + 2, (kb + 2) % GSTAGES);
    }

    // epilogue
#pragma unroll
    for (int mt = 0; mt < 4; mt++) {
#pragma unroll
        for (int rh = 0; rh < 2; rh++) {
            int row = bm + wm + mt * 16 + grp + rh * 8;
#pragma unroll
            for (int nt = 0; nt < 4; nt++) {
                int col = bn + wn + nt * 8 + tig * 2;
                float v0 = acc[mt][nt][rh * 2 + 0] + bias[col];
                float v1 = acc[mt][nt][rh * 2 + 1] + bias[col + 1];
                if (epi == 1) {
                    v0 = fmaxf(v0, 0.f);
                    v1 = fmaxf(v1, 0.f);
                    __half* cp = (__half*)Cout;
                    *reinterpret_cast<__half2*>(&cp[(size_t)row * Ntot + col]) =
                        __floats2half2_rn(v0, v1);
                } else {
                    float* cp = (float*)Cout;
                    *reinterpret_cast<float2*>(&cp[(size_t)row * Ntot + col]) =
                        make_float2(v0, v1);
                }
            }
        }
    }
}

// ---------------- persistent LSTM recurrence (fp16 mma.sync, 256 thr) --------
#define RT_STRIDE 72                       // halfs (144 B rows)
#define WF_SLOTS 8192                      // [k16=64][nb=4][lane=32] x uint2
#define WF_BYTES (WF_SLOTS * 8)            // 64 KB
#define HT_OFF   WF_BYTES
#define HT_BYTES (2 * 128 * RT_STRIDE * 2) // 36864
#define REC_SMEM (WF_BYTES + HT_BYTES)     // 102400

__device__ __forceinline__ void stage_chunk_h(const __half* __restrict__ hsrc,
                                              char* __restrict__ dst,
                                              int chunk, int tid)
{
    const int p = tid & 7;        // 16B piece (8 halfs)
    const int rbase = tid >> 3;   // 0..31
    const __half* src = hsrc + chunk * 64 + p * 8;
#pragma unroll
    for (int w = 0; w < 4; w++) {
        int row = rbase + w * 32;
        unsigned da = (unsigned)__cvta_generic_to_shared(
            dst + (row * RT_STRIDE + p * 8) * 2);
        asm volatile("cp.async.cg.shared.global [%0], [%1], 16;\n"
                     :: "r"(da), "l"(src + (size_t)row * H_));
    }
}

__device__ __forceinline__ void grid_bar(int step) {
    __syncthreads();
    if (threadIdx.x == 0) {
        __threadfence();
        atomicAdd(&g_bar, 1u);
        const unsigned target = (unsigned)NBLK * (step + 1);
        unsigned v;
        do {
            asm volatile("ld.acquire.gpu.global.u32 %0, [%1];"
                         : "=r"(v) : "l"(&g_bar));
        } while (v < target);
    }
    __syncthreads();
}

__global__ void __launch_bounds__(256, 1)
lstm_persistent(const float* __restrict__ xg,
                const float* __restrict__ W_hh,
                const float* __restrict__ b_hh,
                float* __restrict__ hs)
{
    extern __shared__ __align__(16) char rsm[];
    uint2* Wf = (uint2*)rsm;                  // [k16][nb][lane]
    char*  ht = rsm + HT_OFF;                 // [2][128][RT_STRIDE] halfs

    const int tid  = threadIdx.x;
    const int lane = tid & 31;
    const int warp = tid >> 5;                // 0..7
    const int blk  = blockIdx.x;
    const int grp  = lane >> 2;
    const int tig  = lane & 3;
    const int row0 = warp * 16;               // warp's 16 batch rows

    // ---- one-time: W_hh slice as fp16 m16n8k16 B fragments ----
    for (int slot = tid; slot < WF_SLOTS; slot += 256) {
        int ls  = slot & 31;
        int nb  = (slot >> 5) & 3;
        int k16 = slot >> 7;
        int gs = ls >> 2, ts = ls & 3;
        int gcol = nb * H_ + blk * 8 + gs;
        const float* wr = &W_hh[(size_t)gcol * H_ + k16 * 16 + 2 * ts];
        Wf[slot] = make_uint2(packh2(wr[0], wr[1]), packh2(wr[8], wr[9]));
    }

    float bh[8];
#pragma unroll
    for (int n = 0; n < 4; n++) {
        int gc = n * H_ + blk * 8 + 2 * tig;
        bh[2 * n]     = b_hh[gc];
        bh[2 * n + 1] = b_hh[gc + 1];
    }

    float cst[4];
#pragma unroll
    for (int i = 0; i < 4; i++) cst[i] = 0.f;

    // prefetch xg addends for step 0: [n(4)][rh(2)][cc(2)]
    float xgv[16];
#pragma unroll
    for (int n = 0; n < 4; n++)
#pragma unroll
    for (int rh = 0; rh < 2; rh++) {
        int row = row0 + grp + rh * 8;
        size_t base = ((size_t)row * T_) * G4 + n * H_ + blk * 8 + 2 * tig;
        float2 v = *reinterpret_cast<const float2*>(&xg[base]);
        xgv[(n * 2 + rh) * 2]     = v.x;
        xgv[(n * 2 + rh) * 2 + 1] = v.y;
    }

    __syncthreads();

    for (int t = 0; t < T_; t++) {
        const __half* hin  = g_h[t & 1];
        __half*       hout = g_h[(t + 1) & 1];

        float acc[4][4];
#pragma unroll
        for (int n = 0; n < 4; n++)
#pragma unroll
            for (int c = 0; c < 4; c++) acc[n][c] = 0.f;

        stage_chunk_h(hin, ht, 0, tid);
        asm volatile("cp.async.commit_group;\n");

        for (int chunk = 0; chunk < 16; chunk++) {
            if (chunk + 1 < 16) {
                stage_chunk_h(hin, ht + ((chunk + 1) & 1) * 128 * RT_STRIDE * 2,
                              chunk + 1, tid);
                asm volatile("cp.async.commit_group;\n");
                asm volatile("cp.async.wait_group 1;\n");
            } else {
                asm volatile("cp.async.wait_group 0;\n");
            }
            __syncthreads();

            const __half* hb = (const __half*)(ht + (chunk & 1) * 128 * RT_STRIDE * 2);
            const int r = row0 + grp;
#pragma unroll
            for (int j = 0; j < 4; j++) {
                const int koff = j * 16 + 2 * tig;
                uint32_t a0 = *(const uint32_t*)&hb[r * RT_STRIDE + koff];
                uint32_t a1 = *(const uint32_t*)&hb[(r + 8) * RT_STRIDE + koff];
                uint32_t a2 = *(const uint32_t*)&hb[r * RT_STRIDE + koff + 8];
                uint32_t a3 = *(const uint32_t*)&hb[(r + 8) * RT_STRIDE + koff + 8];
                const int k16 = chunk * 4 + j;
#pragma unroll
                for (int nb = 0; nb < 4; nb++) {
                    uint2 b = Wf[(k16 * 4 + nb) * 32 + lane];
                    mma_f16(acc[nb], a0, a1, a2, a3, b.x, b.y);
                }
            }
            __syncthreads();
        }

        // fused LSTM pointwise (c-state in regs), write h (fp16) + hs (fp32)
#pragma unroll
        for (int rh = 0; rh < 2; rh++) {
            int row = row0 + grp + rh * 8;
            int hc  = blk * 8 + 2 * tig;
            float hpair[2];
#pragma unroll
            for (int cc = 0; cc < 2; cc++) {
                int ci = rh * 2 + cc;
                float gi = acc[0][ci] + xgv[(0 * 2 + rh) * 2 + cc] + bh[0 + cc];
                float gf = acc[1][ci] + xgv[(1 * 2 + rh) * 2 + cc] + bh[2 + cc];
                float gg = acc[2][ci] + xgv[(2 * 2 + rh) * 2 + cc] + bh[4 + cc];
                float go = acc[3][ci] + xgv[(3 * 2 + rh) * 2 + cc] + bh[6 + cc];
                float iv = sigmoidf_(gi);
                float fv = sigmoidf_(gf);
                float gv = tanhf(gg);
                float ov = sigmoidf_(go);
                float cn = fv * cst[ci] + iv * gv;
                cst[ci] = cn;
                hpair[cc] = ov * tanhf(cn);
            }
            __half2 hh = __floats2half2_rn(hpair[0], hpair[1]);
            *reinterpret_cast<__half2*>(&hout[(size_t)row * H_ + hc]) = hh;
            // hs stores exactly the fp16-rounded value (consistency with h)
            *reinterpret_cast<float2*>(&hs[((size_t)t * B_ + row) * H_ + hc]) =
                make_float2(__half2float(__low2half(hh)),
                            __half2float(__high2half(hh)));
        }

        if (t < T_ - 1) {
            // prefetch xg for step t+1 BEFORE the barrier (independent of h)
            float xn[16];
#pragma unroll
            for (int n = 0; n < 4; n++)
#pragma unroll
            for (int rh = 0; rh < 2; rh++) {
                int row = row0 + grp + rh * 8;
                size_t base = ((size_t)row * T_ + (t + 1)) * G4 + n * H_ +
                              blk * 8 + 2 * tig;
                float2 v = *reinterpret_cast<const float2*>(&xg[base]);
                xn[(n * 2 + rh) * 2]     = v.x;
                xn[(n * 2 + rh) * 2 + 1] = v.y;
            }
            grid_bar(t);
#pragma unroll
            for (int i = 0; i < 16; i++) xgv[i] = xn[i];
        }
    }
}

// ---------------- classifier ----------------
__global__ void classifier_kernel(const float* __restrict__ hs,
                                  const float* __restrict__ Wc,
                                  const float* __restrict__ bc,
                                  float* __restrict__ out)
{
    __shared__ float sh[H_];
    const int bt = blockIdx.x;
    const int b = bt / T_;
    const int t = bt % T_;
    const float* hrow = hs + ((size_t)t * B_ + b) * H_;
    for (int i = threadIdx.x; i < H_; i += blockDim.x) sh[i] = hrow[i];
    __syncthreads();

    const int warp = threadIdx.x >> 5;
    const int lane = threadIdx.x & 31;
    const int nwarps = blockDim.x >> 5;
    for (int col = warp; col < C_; col += nwarps) {
        const float* w = Wc + (size_t)col * H_;
        float s = 0.f;
        for (int k = lane; k < H_; k += 32) s = fmaf(sh[k], w[k], s);
#pragma unroll
        for (int o = 16; o; o >>= 1) s += __shfl_xor_sync(0xffffffffu, s, o);
        if (lane == 0) out[(size_t)bt * C_ + col] = s + bc[col];
    }
}

// ---------------- launch ----------------
extern "C" void kernel_launch(void* const* d_in, const int* in_sizes, int n_in,
                              void* d_out, int out_size)
{
    (void)in_sizes; (void)n_in; (void)out_size;
    const float* x    = (const float*)d_in[0];
    const float* W1   = (const float*)d_in[1];
    const float* b1   = (const float*)d_in[2];
    const float* W_ih = (const float*)d_in[3];
    const float* b_ih = (const float*)d_in[4];
    const float* W_hh = (const float*)d_in[5];
    const float* b_hh = (const float*)d_in[6];
    const float* Wc   = (const float*)d_in[7];
    const float* bc   = (const float*)d_in[8];
    float* out = (float*)d_out;

    __half *z_p, *xh_p, *w1h_p, *wih_p, *h_p;
    float *xg_p, *hs_p; unsigned* bar_p;
    cudaGetSymbolAddress((void**)&z_p,   g_z);
    cudaGetSymbolAddress((void**)&xg_p,  g_xg);
    cudaGetSymbolAddress((void**)&h_p,   g_h);
    cudaGetSymbolAddress((void**)&hs_p,  g_hs);
    cudaGetSymbolAddress((void**)&xh_p,  g_xh);
    cudaGetSymbolAddress((void**)&w1h_p, g_w1h);
    cudaGetSymbolAddress((void**)&wih_p, g_wih);
    cudaGetSymbolAddress((void**)&bar_p, g_bar);

    cudaMemsetAsync(bar_p, 0, sizeof(unsigned));
    cudaMemsetAsync(h_p, 0, (size_t)B_ * H_ * sizeof(__half));

    // 0) convert inputs to fp16
    {
        int n4 = B_ * T_ * F_ / 4;
        to_half<<<(n4 + 255) / 256, 256>>>((const float4*)x, (__half2*)xh_p, n4);
        n4 = N_ * F_ / 4;
        to_half<<<(n4 + 255) / 256, 256>>>((const float4*)W1, (__half2*)w1h_p, n4);
        n4 = G4 * N_ / 4;
        to_half<<<(n4 + 255) / 256, 256>>>((const float4*)W_ih, (__half2*)wih_p, n4);
    }

    cudaFuncSetAttribute(gemm_h,
                         cudaFuncAttributeMaxDynamicSharedMemorySize, GEMM_SMEM);

    // 1) z = fp16(relu(x @ W1^T + b1)) : M=8192, N=1024, K=2048
    {
        dim3 grid(N_ / 128, (B_ * T_) / 128);
        gemm_h<<<grid, 256, GEMM_SMEM>>>(xh_p, w1h_p, b1, z_p, N_, F_, 1);
    }
    // 2) xg = z @ W_ih^T + b_ih (fp32 out) : M=8192, N=4096, K=1024
    {
        dim3 grid(G4 / 128, (B_ * T_) / 128);
        gemm_h<<<grid, 256, GEMM_SMEM>>>(z_p, wih_p, b_ih, xg_p, G4, N_, 0);
    }
    // 3) persistent recurrence (fp16 tensor cores, one kernel for all steps)
    cudaFuncSetAttribute(lstm_persistent,
                         cudaFuncAttributeMaxDynamicSharedMemorySize, REC_SMEM);
    lstm_persistent<<<NBLK, 256, REC_SMEM>>>(xg_p, W_hh, b_hh, hs_p);

    // 4) classifier
    classifier_kernel<<<B_ * T_, 256>>>(hs_p, Wc, bc, out);
}

// round 6
// speedup vs baseline: 10.7774x; 1.2325x over previous
#include <cuda_runtime.h>
#include <cuda_fp16.h>
#include <math.h>
#include <stdint.h>

// Problem constants
#define B_  128
#define T_  64
#define F_  2048
#define N_  1024
#define H_  1024
#define C_  22
#define G4  (4 * H_)   // 4096
#define NBLK 128       // persistent recurrence blocks

// ---------------- scratch (static device globals; no allocation) ----------------
__device__ __half g_z  [(size_t)B_ * T_ * N_];      // [8192, 1024] fp16
__device__ float  g_xg [(size_t)B_ * T_ * G4];      // [B, T, 4096] fp32
__device__ __half g_h  [2][(size_t)B_ * H_];        // ping/pong hidden (fp16)
__device__ __half g_hs [(size_t)T_ * B_ * H_];      // [T, B, H] fp16
__device__ __half g_xh [(size_t)B_ * T_ * F_];      // fp16 x
__device__ __half g_w1h[(size_t)N_ * F_];           // fp16 W1
__device__ __half g_wih[(size_t)G4 * N_];           // fp16 W_ih
__device__ unsigned g_bar;                          // grid barrier counter

__device__ __forceinline__ float sigmoidf_(float x) {
    return 1.f / (1.f + __expf(-x));
}
__device__ __forceinline__ uint32_t packh2(float a, float b) {
    __half2 h = __floats2half2_rn(a, b);
    return *reinterpret_cast<uint32_t*>(&h);
}
__device__ __forceinline__ void mma_f16(float* acc, uint32_t a0, uint32_t a1,
                                        uint32_t a2, uint32_t a3,
                                        uint32_t b0, uint32_t b1)
{
    asm volatile(
        "mma.sync.aligned.m16n8k16.row.col.f32.f16.f16.f32 "
        "{%0,%1,%2,%3},{%4,%5,%6,%7},{%8,%9},{%0,%1,%2,%3};"
        : "+f"(acc[0]), "+f"(acc[1]), "+f"(acc[2]), "+f"(acc[3])
        : "r"(a0), "r"(a1), "r"(a2), "r"(a3), "r"(b0), "r"(b1));
}

// ---------------- fp32 -> fp16 convert ----------------
__global__ void to_half(const float4* __restrict__ in,
                        __half2* __restrict__ out, int n4)
{
    int i = blockIdx.x * blockDim.x + threadIdx.x;
    if (i >= n4) return;
    float4 v = in[i];
    out[2 * i]     = __floats2half2_rn(v.x, v.y);
    out[2 * i + 1] = __floats2half2_rn(v.z, v.w);
}

// ============================================================================
// fp16 NT GEMM (mma.sync m16n8k16): C[m,n] = sum_k A[m,k]*B[n,k] (+bias)
// BM=BN=128, BK=64 halfs, 256 threads (8 warps 2x4), 3-stage, 2 CTAs/SM
// epi: 0 = +bias, write fp32 ; 1 = relu(+bias), write fp16
// ============================================================================
#define GBK 64
#define GSTR 72                       // halfs per smem row (144 B, bank-free)
#define GST_BYTES (128 * GSTR * 2)    // 18432 per matrix per stage
#define GSTAGE_BYTES (2 * GST_BYTES)  // 36864
#define GSTAGES 3
#define GEMM_SMEM (GSTAGES * GSTAGE_BYTES)  // 110592

__global__ void __launch_bounds__(256, 2)
gemm_h(const __half* __restrict__ A, const __half* __restrict__ Bw,
       const float* __restrict__ bias, void* __restrict__ Cout,
       int Ntot, int K, int epi)
{
    extern __shared__ __align__(16) char gsm[];

    const int tid = threadIdx.x;
    const int lane = tid & 31, warp = tid >> 5;
    const int bm = blockIdx.y * 128, bn = blockIdx.x * 128;
    const int wm = (warp & 1) * 64, wn = (warp >> 1) * 32;
    const int grp = lane >> 2, tig = lane & 3;
    const int nk = K / GBK;

    float acc[4][4][4];
#pragma unroll
    for (int a = 0; a < 4; a++)
#pragma unroll
        for (int b = 0; b < 4; b++)
#pragma unroll
            for (int c = 0; c < 4; c++) acc[a][b][c] = 0.f;

    auto load_stage = [&](int kb, int buf) {
        const int k0 = kb * GBK;
        char* as = gsm + buf * GSTAGE_BYTES;
        char* bs = as + GST_BYTES;
        const int r = tid >> 3, p = tid & 7;   // 128 rows, 8x16B pieces
#pragma unroll
        for (int w = 0; w < 4; w++) {
            int row = r + w * 32;
            unsigned da = (unsigned)__cvta_generic_to_shared(
                as + (row * GSTR + p * 8) * 2);
            asm volatile("cp.async.cg.shared.global [%0], [%1], 16;\n"
                         :: "r"(da), "l"(&A[(size_t)(bm + row) * K + k0 + p * 8]));
            unsigned db = (unsigned)__cvta_generic_to_shared(
                bs + (row * GSTR + p * 8) * 2);
            asm volatile("cp.async.cg.shared.global [%0], [%1], 16;\n"
                         :: "r"(db), "l"(&Bw[(size_t)(bn + row) * K + k0 + p * 8]));
        }
        asm volatile("cp.async.commit_group;\n");
    };

    load_stage(0, 0);
    if (nk > 1) load_stage(1, 1);

    for (int kb = 0; kb < nk; kb++) {
        if (kb == nk - 1) asm volatile("cp.async.wait_group 0;\n");
        else              asm volatile("cp.async.wait_group 1;\n");
        __syncthreads();

        const __half* a_s = (const __half*)(gsm + (kb % GSTAGES) * GSTAGE_BYTES);
        const __half* b_s = (const __half*)((const char*)a_s + GST_BYTES);
#pragma unroll
        for (int s = 0; s < 4; s++) {
            const int koff = s * 16 + 2 * tig;
            uint32_t af[4][4], bf[4][2];
#pragma unroll
            for (int mt = 0; mt < 4; mt++) {
                int r = wm + mt * 16 + grp;
                af[mt][0] = *(const uint32_t*)&a_s[r * GSTR + koff];
                af[mt][1] = *(const uint32_t*)&a_s[(r + 8) * GSTR + koff];
                af[mt][2] = *(const uint32_t*)&a_s[r * GSTR + koff + 8];
                af[mt][3] = *(const uint32_t*)&a_s[(r + 8) * GSTR + koff + 8];
            }
#pragma unroll
            for (int nt = 0; nt < 4; nt++) {
                int n = wn + nt * 8 + grp;
                bf[nt][0] = *(const uint32_t*)&b_s[n * GSTR + koff];
                bf[nt][1] = *(const uint32_t*)&b_s[n * GSTR + koff + 8];
            }
#pragma unroll
            for (int mt = 0; mt < 4; mt++)
#pragma unroll
                for (int nt = 0; nt < 4; nt++)
                    mma_f16(acc[mt][nt], af[mt][0], af[mt][1], af[mt][2],
                            af[mt][3], bf[nt][0], bf[nt][1]);
        }
        __syncthreads();
        if (kb + 2 < nk) load_stage(kb + 2, (kb + 2) % GSTAGES);
    }

    // epilogue
#pragma unroll
    for (int mt = 0; mt < 4; mt++) {
#pragma unroll
        for (int rh = 0; rh < 2; rh++) {
            int row = bm + wm + mt * 16 + grp + rh * 8;
#pragma unroll
            for (int nt = 0; nt < 4; nt++) {
                int col = bn + wn + nt * 8 + tig * 2;
                float v0 = acc[mt][nt][rh * 2 + 0] + bias[col];
                float v1 = acc[mt][nt][rh * 2 + 1] + bias[col + 1];
                if (epi == 1) {
                    v0 = fmaxf(v0, 0.f);
                    v1 = fmaxf(v1, 0.f);
                    __half* cp = (__half*)Cout;
                    *reinterpret_cast<__half2*>(&cp[(size_t)row * Ntot + col]) =
                        __floats2half2_rn(v0, v1);
                } else {
                    float* cp = (float*)Cout;
                    *reinterpret_cast<float2*>(&cp[(size_t)row * Ntot + col]) =
                        make_float2(v0, v1);
                }
            }
        }
    }
}

// ---------------- persistent LSTM recurrence (fp16, 64 rows x 64 cols) -------
// CTA blk: rowHalf = blk&1 -> batch rows [rowHalf*64, +64)
//          colBlk  = blk>>1 -> hidden units [colBlk*16, +16) (x4 gates = 64 cols)
// Warp: wm=(warp&3)*16 row tile, wg=warp>>2 hidden group of 8
#define RT_STRIDE 136                        // halfs per staged row (272 B)
#define WF_SLOTS 16384                       // [k16=64][wg=2][nb=4][lane=32] uint2
#define WF_BYTES (WF_SLOTS * 8)              // 131072
#define HT_OFF   WF_BYTES
#define HT_BYTES (2 * 64 * RT_STRIDE * 2)    // 34816
#define REC_SMEM (WF_BYTES + HT_BYTES)       // 165888

__device__ __forceinline__ void stage_chunk_h(const __half* __restrict__ hsrc,
                                              char* __restrict__ dst,
                                              int chunk, int tid)
{
    const int p = tid & 15;       // 16B piece -> cols p*8..p*8+7 of 128
    const int r0 = tid >> 4;      // 0..15
    const __half* src = hsrc + chunk * 128 + p * 8;
#pragma unroll
    for (int w = 0; w < 4; w++) {
        int row = r0 + w * 16;
        unsigned da = (unsigned)__cvta_generic_to_shared(
            dst + (row * RT_STRIDE + p * 8) * 2);
        asm volatile("cp.async.cg.shared.global [%0], [%1], 16;\n"
                     :: "r"(da), "l"(src + (size_t)row * H_));
    }
}

__device__ __forceinline__ void grid_bar(int step) {
    __syncthreads();
    if (threadIdx.x == 0) {
        __threadfence();
        atomicAdd(&g_bar, 1u);
        const unsigned target = (unsigned)NBLK * (step + 1);
        unsigned v;
        do {
            asm volatile("ld.acquire.gpu.global.u32 %0, [%1];"
                         : "=r"(v) : "l"(&g_bar));
        } while (v < target);
    }
    __syncthreads();
}

__global__ void __launch_bounds__(256, 1)
lstm_persistent(const float* __restrict__ xg,
                const float* __restrict__ W_hh,
                const float* __restrict__ b_hh,
                __half* __restrict__ hs)
{
    extern __shared__ __align__(16) char rsm[];
    uint2* Wf = (uint2*)rsm;                  // [k16][wg][nb][lane]
    char*  ht = rsm + HT_OFF;                 // [2][64][RT_STRIDE] halfs

    const int tid  = threadIdx.x;
    const int lane = tid & 31;
    const int warp = tid >> 5;                // 0..7
    const int blk  = blockIdx.x;
    const int rowHalf = blk & 1;
    const int colBlk  = blk >> 1;             // 0..63
    const int grp  = lane >> 2;
    const int tig  = lane & 3;
    const int wm   = (warp & 3) * 16;         // local row tile
    const int wg   = warp >> 2;               // hidden group (0/1)
    const int row0 = rowHalf * 64 + wm;       // global batch row base
    const int hb0  = colBlk * 16 + wg * 8;    // hidden base for this warp

    // ---- one-time: W_hh slice as fp16 m16n8k16 B fragments ----
    for (int slot = tid; slot < WF_SLOTS; slot += 256) {
        int ls   = slot & 31;
        int idx2 = slot >> 5;
        int nb   = idx2 & 3;
        int wgf  = (idx2 >> 2) & 1;
        int k16  = idx2 >> 3;
        int gs = ls >> 2, ts = ls & 3;
        int gcol = nb * H_ + colBlk * 16 + wgf * 8 + gs;
        const float* wr = &W_hh[(size_t)gcol * H_ + k16 * 16 + 2 * ts];
        Wf[slot] = make_uint2(packh2(wr[0], wr[1]), packh2(wr[8], wr[9]));
    }

    float bh[8];
#pragma unroll
    for (int n = 0; n < 4; n++) {
        int gc = n * H_ + hb0 + 2 * tig;
        bh[2 * n]     = b_hh[gc];
        bh[2 * n + 1] = b_hh[gc + 1];
    }

    float cst[4];
#pragma unroll
    for (int i = 0; i < 4; i++) cst[i] = 0.f;

    // prefetch xg addends for step 0: [n(4)][rh(2)][cc(2)]
    float xgv[16];
#pragma unroll
    for (int n = 0; n < 4; n++)
#pragma unroll
    for (int rh = 0; rh < 2; rh++) {
        int row = row0 + grp + rh * 8;
        size_t base = ((size_t)row * T_) * G4 + n * H_ + hb0 + 2 * tig;
        float2 v = *reinterpret_cast<const float2*>(&xg[base]);
        xgv[(n * 2 + rh) * 2]     = v.x;
        xgv[(n * 2 + rh) * 2 + 1] = v.y;
    }

    __syncthreads();

    for (int t = 0; t < T_; t++) {
        const __half* hin  = g_h[t & 1] + (size_t)rowHalf * 64 * H_;
        __half*       hout = g_h[(t + 1) & 1];

        float acc[4][4];
#pragma unroll
        for (int n = 0; n < 4; n++)
#pragma unroll
            for (int c = 0; c < 4; c++) acc[n][c] = 0.f;

        stage_chunk_h(hin, ht, 0, tid);
        asm volatile("cp.async.commit_group;\n");

        for (int chunk = 0; chunk < 8; chunk++) {
            if (chunk + 1 < 8) {
                stage_chunk_h(hin, ht + ((chunk + 1) & 1) * 64 * RT_STRIDE * 2,
                              chunk + 1, tid);
                asm volatile("cp.async.commit_group;\n");
                asm volatile("cp.async.wait_group 1;\n");
            } else {
                asm volatile("cp.async.wait_group 0;\n");
            }
            __syncthreads();

            const __half* hb = (const __half*)(ht + (chunk & 1) * 64 * RT_STRIDE * 2);
            const int r = wm + grp;
#pragma unroll
            for (int j = 0; j < 8; j++) {
                const int koff = j * 16 + 2 * tig;
                uint32_t a0 = *(const uint32_t*)&hb[r * RT_STRIDE + koff];
                uint32_t a1 = *(const uint32_t*)&hb[(r + 8) * RT_STRIDE + koff];
                uint32_t a2 = *(const uint32_t*)&hb[r * RT_STRIDE + koff + 8];
                uint32_t a3 = *(const uint32_t*)&hb[(r + 8) * RT_STRIDE + koff + 8];
                const int k16 = chunk * 8 + j;
#pragma unroll
                for (int nb = 0; nb < 4; nb++) {
                    uint2 b = Wf[((k16 * 2 + wg) * 4 + nb) * 32 + lane];
                    mma_f16(acc[nb], a0, a1, a2, a3, b.x, b.y);
                }
            }
            __syncthreads();
        }

        // fused LSTM pointwise (c-state in regs), write h + hs (fp16)
#pragma unroll
        for (int rh = 0; rh < 2; rh++) {
            int row = row0 + grp + rh * 8;
            int hc  = hb0 + 2 * tig;
            float hpair[2];
#pragma unroll
            for (int cc = 0; cc < 2; cc++) {
                int ci = rh * 2 + cc;
                float gi = acc[0][ci] + xgv[(0 * 2 + rh) * 2 + cc] + bh[0 + cc];
                float gf = acc[1][ci] + xgv[(1 * 2 + rh) * 2 + cc] + bh[2 + cc];
                float gg = acc[2][ci] + xgv[(2 * 2 + rh) * 2 + cc] + bh[4 + cc];
                float go = acc[3][ci] + xgv[(3 * 2 + rh) * 2 + cc] + bh[6 + cc];
                float iv = sigmoidf_(gi);
                float fv = sigmoidf_(gf);
                float gv = tanhf(gg);
                float ov = sigmoidf_(go);
                float cn = fv * cst[ci] + iv * gv;
                cst[ci] = cn;
                hpair[cc] = ov * tanhf(cn);
            }
            __half2 hh = __floats2half2_rn(hpair[0], hpair[1]);
            *reinterpret_cast<__half2*>(&hout[(size_t)row * H_ + hc]) = hh;
            *reinterpret_cast<__half2*>(&hs[((size_t)t * B_ + row) * H_ + hc]) = hh;
        }

        if (t < T_ - 1) {
            // prefetch xg for step t+1 BEFORE the barrier (independent of h)
            float xn[16];
#pragma unroll
            for (int n = 0; n < 4; n++)
#pragma unroll
            for (int rh = 0; rh < 2; rh++) {
                int row = row0 + grp + rh * 8;
                size_t base = ((size_t)row * T_ + (t + 1)) * G4 + n * H_ +
                              hb0 + 2 * tig;
                float2 v = *reinterpret_cast<const float2*>(&xg[base]);
                xn[(n * 2 + rh) * 2]     = v.x;
                xn[(n * 2 + rh) * 2 + 1] = v.y;
            }
            grid_bar(t);
#pragma unroll
            for (int i = 0; i < 16; i++) xgv[i] = xn[i];
        }
    }
}

// ---------------- classifier (fp16 hs) ----------------
__global__ void classifier_kernel(const __half* __restrict__ hs,
                                  const float* __restrict__ Wc,
                                  const float* __restrict__ bc,
                                  float* __restrict__ out)
{
    __shared__ float sh[H_];
    const int bt = blockIdx.x;
    const int b = bt / T_;
    const int t = bt % T_;
    const __half* hrow = hs + ((size_t)t * B_ + b) * H_;
    for (int i = threadIdx.x; i < H_ / 2; i += blockDim.x) {
        __half2 v = *reinterpret_cast<const __half2*>(&hrow[2 * i]);
        sh[2 * i]     = __half2float(__low2half(v));
        sh[2 * i + 1] = __half2float(__high2half(v));
    }
    __syncthreads();

    const int warp = threadIdx.x >> 5;
    const int lane = threadIdx.x & 31;
    const int nwarps = blockDim.x >> 5;
    for (int col = warp; col < C_; col += nwarps) {
        const float* w = Wc + (size_t)col * H_;
        float s = 0.f;
        for (int k = lane; k < H_; k += 32) s = fmaf(sh[k], w[k], s);
#pragma unroll
        for (int o = 16; o; o >>= 1) s += __shfl_xor_sync(0xffffffffu, s, o);
        if (lane == 0) out[(size_t)bt * C_ + col] = s + bc[col];
    }
}

// ---------------- launch ----------------
extern "C" void kernel_launch(void* const* d_in, const int* in_sizes, int n_in,
                              void* d_out, int out_size)
{
    (void)in_sizes; (void)n_in; (void)out_size;
    const float* x    = (const float*)d_in[0];
    const float* W1   = (const float*)d_in[1];
    const float* b1   = (const float*)d_in[2];
    const float* W_ih = (const float*)d_in[3];
    const float* b_ih = (const float*)d_in[4];
    const float* W_hh = (const float*)d_in[5];
    const float* b_hh = (const float*)d_in[6];
    const float* Wc   = (const float*)d_in[7];
    const float* bc   = (const float*)d_in[8];
    float* out = (float*)d_out;

    __half *z_p, *xh_p, *w1h_p, *wih_p, *h_p, *hs_p;
    float *xg_p; unsigned* bar_p;
    cudaGetSymbolAddress((void**)&z_p,   g_z);
    cudaGetSymbolAddress((void**)&xg_p,  g_xg);
    cudaGetSymbolAddress((void**)&h_p,   g_h);
    cudaGetSymbolAddress((void**)&hs_p,  g_hs);
    cudaGetSymbolAddress((void**)&xh_p,  g_xh);
    cudaGetSymbolAddress((void**)&w1h_p, g_w1h);
    cudaGetSymbolAddress((void**)&wih_p, g_wih);
    cudaGetSymbolAddress((void**)&bar_p, g_bar);

    cudaMemsetAsync(bar_p, 0, sizeof(unsigned));
    cudaMemsetAsync(h_p, 0, (size_t)B_ * H_ * sizeof(__half));

    // 0) convert inputs to fp16
    {
        int n4 = B_ * T_ * F_ / 4;
        to_half<<<(n4 + 255) / 256, 256>>>((const float4*)x, (__half2*)xh_p, n4);
        n4 = N_ * F_ / 4;
        to_half<<<(n4 + 255) / 256, 256>>>((const float4*)W1, (__half2*)w1h_p, n4);
        n4 = G4 * N_ / 4;
        to_half<<<(n4 + 255) / 256, 256>>>((const float4*)W_ih, (__half2*)wih_p, n4);
    }

    cudaFuncSetAttribute(gemm_h,
                         cudaFuncAttributeMaxDynamicSharedMemorySize, GEMM_SMEM);

    // 1) z = fp16(relu(x @ W1^T + b1)) : M=8192, N=1024, K=2048
    {
        dim3 grid(N_ / 128, (B_ * T_) / 128);
        gemm_h<<<grid, 256, GEMM_SMEM>>>(xh_p, w1h_p, b1, z_p, N_, F_, 1);
    }
    // 2) xg = z @ W_ih^T + b_ih (fp32 out) : M=8192, N=4096, K=1024
    {
        dim3 grid(G4 / 128, (B_ * T_) / 128);
        gemm_h<<<grid, 256, GEMM_SMEM>>>(z_p, wih_p, b_ih, xg_p, G4, N_, 0);
    }
    // 3) persistent recurrence (fp16 tensor cores, one kernel for all steps)
    cudaFuncSetAttribute(lstm_persistent,
                         cudaFuncAttributeMaxDynamicSharedMemorySize, REC_SMEM);
    lstm_persistent<<<NBLK, 256, REC_SMEM>>>(xg_p, W_hh, b_hh, hs_p);

    // 4) classifier
    classifier_kernel<<<B_ * T_, 256>>>(hs_p, Wc, bc, out);
}

// round 7
// speedup vs baseline: 11.6116x; 1.0774x over previous
#include <cuda_runtime.h>
#include <cuda_fp16.h>
#include <math.h>
#include <stdint.h>

// Problem constants
#define B_  128
#define T_  64
#define F_  2048
#define N_  1024
#define H_  1024
#define C_  22
#define G4  (4 * H_)   // 4096
#define NBLK 128       // persistent recurrence blocks

// ---------------- scratch (static device globals; no allocation) ----------------
__device__ __half g_z  [(size_t)B_ * T_ * N_];      // [8192, 1024] fp16
__device__ float  g_xg [(size_t)B_ * T_ * G4];      // [B, T, 4096] fp32
__device__ __half g_h  [2][(size_t)B_ * H_];        // ping/pong hidden (fp16)
__device__ __half g_hs [(size_t)T_ * B_ * H_];      // [T, B, H] fp16
__device__ __half g_xh [(size_t)B_ * T_ * F_];      // fp16 x
__device__ __half g_w1h[(size_t)N_ * F_];           // fp16 W1
__device__ __half g_wih[(size_t)G4 * N_];           // fp16 W_ih
__device__ __half g_wch[24 * H_];                   // fp16 Wc padded to 24 rows
__device__ unsigned g_bar[2];                       // per-rowHalf barrier counters

__device__ __forceinline__ float sigmoidf_(float x) {
    return 1.f / (1.f + __expf(-x));
}
__device__ __forceinline__ uint32_t packh2(float a, float b) {
    __half2 h = __floats2half2_rn(a, b);
    return *reinterpret_cast<uint32_t*>(&h);
}
__device__ __forceinline__ void mma_f16(float* acc, uint32_t a0, uint32_t a1,
                                        uint32_t a2, uint32_t a3,
                                        uint32_t b0, uint32_t b1)
{
    asm volatile(
        "mma.sync.aligned.m16n8k16.row.col.f32.f16.f16.f32 "
        "{%0,%1,%2,%3},{%4,%5,%6,%7},{%8,%9},{%0,%1,%2,%3};"
        : "+f"(acc[0]), "+f"(acc[1]), "+f"(acc[2]), "+f"(acc[3])
        : "r"(a0), "r"(a1), "r"(a2), "r"(a3), "r"(b0), "r"(b1));
}
#define LDSM4(r0, r1, r2, r3, addr)                                         \
    asm volatile("ldmatrix.sync.aligned.m8n8.x4.shared.b16 {%0,%1,%2,%3}, [%4];" \
                 : "=r"(r0), "=r"(r1), "=r"(r2), "=r"(r3) : "r"(addr))

// ---------------- fp32 -> fp16 convert ----------------
__global__ void to_half(const float4* __restrict__ in,
                        __half2* __restrict__ out, int n4)
{
    int i = blockIdx.x * blockDim.x + threadIdx.x;
    if (i >= n4) return;
    float4 v = in[i];
    out[2 * i]     = __floats2half2_rn(v.x, v.y);
    out[2 * i + 1] = __floats2half2_rn(v.z, v.w);
}
__global__ void prep_wc(const float* __restrict__ Wc, __half* __restrict__ out)
{
    int c = blockIdx.x;   // 0..23
    for (int k = threadIdx.x; k < H_; k += blockDim.x)
        out[c * H_ + k] = (c < C_) ? __float2half(Wc[(size_t)c * H_ + k])
                                   : __float2half(0.f);
}

// ============================================================================
// fp16 NT GEMM (mma.sync m16n8k16, ldmatrix): C[m,n]=sum_k A[m,k]*B[n,k](+bias)
// BM=BN=128, BK=64 halfs, 256 threads (8 warps 2x4), 3-stage
// epi: 0 = +bias, write fp32 ; 1 = relu(+bias), write fp16
// ============================================================================
#define GBK 64
#define GSTR 72                       // halfs per smem row (144 B, bank-free)
#define GST_BYTES (128 * GSTR * 2)    // 18432 per matrix per stage
#define GSTAGE_BYTES (2 * GST_BYTES)  // 36864
#define GSTAGES 3
#define GEMM_SMEM (GSTAGES * GSTAGE_BYTES)  // 110592

__global__ void __launch_bounds__(256, 2)
gemm_h(const __half* __restrict__ A, const __half* __restrict__ Bw,
       const float* __restrict__ bias, void* __restrict__ Cout,
       int Ntot, int K, int epi)
{
    extern __shared__ __align__(16) char gsm[];
    const uint32_t smem_u32 = (uint32_t)__cvta_generic_to_shared(gsm);

    const int tid = threadIdx.x;
    const int lane = tid & 31, warp = tid >> 5;
    const int bm = blockIdx.y * 128, bn = blockIdx.x * 128;
    const int wm = (warp & 1) * 64, wn = (warp >> 1) * 32;
    const int grp = lane >> 2, tig = lane & 3;
    const int nk = K / GBK;

    // ldmatrix per-lane addressing
    const int aRow = ((lane >> 3) & 1) * 8 + (lane & 7);
    const int aCol = (lane >> 4) * 8;
    const int bRow = (lane & 7) + (lane >> 4) * 8;
    const int bCol = ((lane >> 3) & 1) * 8;

    float acc[4][4][4];
#pragma unroll
    for (int a = 0; a < 4; a++)
#pragma unroll
        for (int b = 0; b < 4; b++)
#pragma unroll
            for (int c = 0; c < 4; c++) acc[a][b][c] = 0.f;

    auto load_stage = [&](int kb, int buf) {
        const int k0 = kb * GBK;
        char* as = gsm + buf * GSTAGE_BYTES;
        char* bs = as + GST_BYTES;
        const int r = tid >> 3, p = tid & 7;   // 128 rows, 8x16B pieces
#pragma unroll
        for (int w = 0; w < 4; w++) {
            int row = r + w * 32;
            unsigned da = (unsigned)__cvta_generic_to_shared(
                as + (row * GSTR + p * 8) * 2);
            asm volatile("cp.async.cg.shared.global [%0], [%1], 16;\n"
                         :: "r"(da), "l"(&A[(size_t)(bm + row) * K + k0 + p * 8]));
            unsigned db = (unsigned)__cvta_generic_to_shared(
                bs + (row * GSTR + p * 8) * 2);
            asm volatile("cp.async.cg.shared.global [%0], [%1], 16;\n"
                         :: "r"(db), "l"(&Bw[(size_t)(bn + row) * K + k0 + p * 8]));
        }
        asm volatile("cp.async.commit_group;\n");
    };

    load_stage(0, 0);
    if (nk > 1) load_stage(1, 1);

    for (int kb = 0; kb < nk; kb++) {
        if (kb == nk - 1) asm volatile("cp.async.wait_group 0;\n");
        else              asm volatile("cp.async.wait_group 1;\n");
        __syncthreads();

        const uint32_t a_b = smem_u32 + (kb % GSTAGES) * GSTAGE_BYTES;
        const uint32_t b_b = a_b + GST_BYTES;
#pragma unroll
        for (int s = 0; s < 4; s++) {
            const int koff = s * 16;
            uint32_t af[4][4], bf[4][2];
#pragma unroll
            for (int mt = 0; mt < 4; mt++) {
                uint32_t addr = a_b +
                    ((wm + mt * 16 + aRow) * GSTR + koff + aCol) * 2;
                LDSM4(af[mt][0], af[mt][1], af[mt][2], af[mt][3], addr);
            }
#pragma unroll
            for (int p = 0; p < 2; p++) {
                uint32_t addr = b_b +
                    ((wn + p * 16 + bRow) * GSTR + koff + bCol) * 2;
                LDSM4(bf[2 * p][0], bf[2 * p][1], bf[2 * p + 1][0],
                      bf[2 * p + 1][1], addr);
            }
#pragma unroll
            for (int mt = 0; mt < 4; mt++)
#pragma unroll
                for (int nt = 0; nt < 4; nt++)
                    mma_f16(acc[mt][nt], af[mt][0], af[mt][1], af[mt][2],
                            af[mt][3], bf[nt][0], bf[nt][1]);
        }
        __syncthreads();
        if (kb + 2 < nk) load_stage(kb + 2, (kb + 2) % GSTAGES);
    }

    // epilogue
#pragma unroll
    for (int mt = 0; mt < 4; mt++) {
#pragma unroll
        for (int rh = 0; rh < 2; rh++) {
            int row = bm + wm + mt * 16 + grp + rh * 8;
#pragma unroll
            for (int nt = 0; nt < 4; nt++) {
                int col = bn + wn + nt * 8 + tig * 2;
                float v0 = acc[mt][nt][rh * 2 + 0] + bias[col];
                float v1 = acc[mt][nt][rh * 2 + 1] + bias[col + 1];
                if (epi == 1) {
                    v0 = fmaxf(v0, 0.f);
                    v1 = fmaxf(v1, 0.f);
                    __half* cp = (__half*)Cout;
                    *reinterpret_cast<__half2*>(&cp[(size_t)row * Ntot + col]) =
                        __floats2half2_rn(v0, v1);
                } else {
                    float* cp = (float*)Cout;
                    *reinterpret_cast<float2*>(&cp[(size_t)row * Ntot + col]) =
                        make_float2(v0, v1);
                }
            }
        }
    }
}

// ---------------- persistent LSTM recurrence (fp16, 64 rows x 64 cols) -------
#define RT_STRIDE 136                        // halfs per staged row (272 B)
#define WF_SLOTS 16384                       // [k16=64][wg=2][nb=4][lane=32] uint2
#define WF_BYTES (WF_SLOTS * 8)              // 131072
#define HT_OFF   WF_BYTES
#define HT_BYTES (2 * 64 * RT_STRIDE * 2)    // 34816
#define REC_SMEM (WF_BYTES + HT_BYTES)       // 165888

__device__ __forceinline__ void stage_chunk_h(const __half* __restrict__ hsrc,
                                              char* __restrict__ dst,
                                              int chunk, int tid)
{
    const int p = tid & 15;       // 16B piece -> cols p*8..p*8+7 of 128
    const int r0 = tid >> 4;      // 0..15
    const __half* src = hsrc + chunk * 128 + p * 8;
#pragma unroll
    for (int w = 0; w < 4; w++) {
        int row = r0 + w * 16;
        unsigned da = (unsigned)__cvta_generic_to_shared(
            dst + (row * RT_STRIDE + p * 8) * 2);
        asm volatile("cp.async.cg.shared.global [%0], [%1], 16;\n"
                     :: "r"(da), "l"(src + (size_t)row * H_));
    }
}

__device__ __forceinline__ void grid_bar_half(int step, int rowHalf) {
    __syncthreads();
    if (threadIdx.x == 0) {
        __threadfence();
        atomicAdd(&g_bar[rowHalf], 1u);
        const unsigned target = 64u * (step + 1);
        unsigned v;
        do {
            asm volatile("ld.acquire.gpu.global.u32 %0, [%1];"
                         : "=r"(v) : "l"(&g_bar[rowHalf]));
        } while (v < target);
    }
    __syncthreads();
}

__global__ void __launch_bounds__(256, 1)
lstm_persistent(const float* __restrict__ xg,
                const float* __restrict__ W_hh,
                const float* __restrict__ b_hh,
                __half* __restrict__ hs)
{
    extern __shared__ __align__(16) char rsm[];
    uint2* Wf = (uint2*)rsm;                  // [k16][wg][nb][lane]
    const uint32_t rsm_u32 = (uint32_t)__cvta_generic_to_shared(rsm);

    const int tid  = threadIdx.x;
    const int lane = tid & 31;
    const int warp = tid >> 5;                // 0..7
    const int blk  = blockIdx.x;
    const int rowHalf = blk & 1;
    const int colBlk  = blk >> 1;             // 0..63
    const int grp  = lane >> 2;
    const int tig  = lane & 3;
    const int wm   = (warp & 3) * 16;         // local row tile
    const int wg   = warp >> 2;               // hidden group (0/1)
    const int row0 = rowHalf * 64 + wm;       // global batch row base
    const int hb0  = colBlk * 16 + wg * 8;    // hidden base for this warp

    // ldmatrix per-lane addressing for A (h) fragments
    const int aRow = wm + ((lane >> 3) & 1) * 8 + (lane & 7);
    const int aCol = (lane >> 4) * 8;

    // ---- one-time: W_hh slice as fp16 m16n8k16 B fragments ----
    for (int slot = tid; slot < WF_SLOTS; slot += 256) {
        int ls   = slot & 31;
        int idx2 = slot >> 5;
        int nb   = idx2 & 3;
        int wgf  = (idx2 >> 2) & 1;
        int k16  = idx2 >> 3;
        int gs = ls >> 2, ts = ls & 3;
        int gcol = nb * H_ + colBlk * 16 + wgf * 8 + gs;
        const float* wr = &W_hh[(size_t)gcol * H_ + k16 * 16 + 2 * ts];
        Wf[slot] = make_uint2(packh2(wr[0], wr[1]), packh2(wr[8], wr[9]));
    }

    float bh[8];
#pragma unroll
    for (int n = 0; n < 4; n++) {
        int gc = n * H_ + hb0 + 2 * tig;
        bh[2 * n]     = b_hh[gc];
        bh[2 * n + 1] = b_hh[gc + 1];
    }

    float cst[4];
#pragma unroll
    for (int i = 0; i < 4; i++) cst[i] = 0.f;

    // prefetch xg addends for step 0
    float xgv[16];
#pragma unroll
    for (int n = 0; n < 4; n++)
#pragma unroll
    for (int rh = 0; rh < 2; rh++) {
        int row = row0 + grp + rh * 8;
        size_t base = ((size_t)row * T_) * G4 + n * H_ + hb0 + 2 * tig;
        float2 v = *reinterpret_cast<const float2*>(&xg[base]);
        xgv[(n * 2 + rh) * 2]     = v.x;
        xgv[(n * 2 + rh) * 2 + 1] = v.y;
    }

    __syncthreads();

    for (int t = 0; t < T_; t++) {
        const __half* hin  = g_h[t & 1] + (size_t)rowHalf * 64 * H_;
        __half*       hout = g_h[(t + 1) & 1];

        float acc[4][4];
#pragma unroll
        for (int n = 0; n < 4; n++)
#pragma unroll
            for (int c = 0; c < 4; c++) acc[n][c] = 0.f;

        stage_chunk_h(hin, rsm + HT_OFF, 0, tid);
        asm volatile("cp.async.commit_group;\n");

        for (int chunk = 0; chunk < 8; chunk++) {
            if (chunk + 1 < 8) {
                stage_chunk_h(hin,
                    rsm + HT_OFF + ((chunk + 1) & 1) * 64 * RT_STRIDE * 2,
                    chunk + 1, tid);
                asm volatile("cp.async.commit_group;\n");
                asm volatile("cp.async.wait_group 1;\n");
            } else {
                asm volatile("cp.async.wait_group 0;\n");
            }
            __syncthreads();

            const uint32_t hb_b = rsm_u32 + HT_OFF +
                                  (chunk & 1) * 64 * RT_STRIDE * 2;
#pragma unroll
            for (int j = 0; j < 8; j++) {
                uint32_t a0, a1, a2, a3;
                uint32_t addr = hb_b + (aRow * RT_STRIDE + j * 16 + aCol) * 2;
                LDSM4(a0, a1, a2, a3, addr);
                const int k16 = chunk * 8 + j;
#pragma unroll
                for (int nb = 0; nb < 4; nb++) {
                    uint2 b = Wf[((k16 * 2 + wg) * 4 + nb) * 32 + lane];
                    mma_f16(acc[nb], a0, a1, a2, a3, b.x, b.y);
                }
            }
            __syncthreads();
        }

        // fused LSTM pointwise (c-state in regs), write h + hs (fp16)
#pragma unroll
        for (int rh = 0; rh < 2; rh++) {
            int row = row0 + grp + rh * 8;
            int hc  = hb0 + 2 * tig;
            float hpair[2];
#pragma unroll
            for (int cc = 0; cc < 2; cc++) {
                int ci = rh * 2 + cc;
                float gi = acc[0][ci] + xgv[(0 * 2 + rh) * 2 + cc] + bh[0 + cc];
                float gf = acc[1][ci] + xgv[(1 * 2 + rh) * 2 + cc] + bh[2 + cc];
                float gg = acc[2][ci] + xgv[(2 * 2 + rh) * 2 + cc] + bh[4 + cc];
                float go = acc[3][ci] + xgv[(3 * 2 + rh) * 2 + cc] + bh[6 + cc];
                float iv = sigmoidf_(gi);
                float fv = sigmoidf_(gf);
                float gv = tanhf(gg);
                float ov = sigmoidf_(go);
                float cn = fv * cst[ci] + iv * gv;
                cst[ci] = cn;
                hpair[cc] = ov * tanhf(cn);
            }
            __half2 hh = __floats2half2_rn(hpair[0], hpair[1]);
            *reinterpret_cast<__half2*>(&hout[(size_t)row * H_ + hc]) = hh;
            *reinterpret_cast<__half2*>(&hs[((size_t)t * B_ + row) * H_ + hc]) = hh;
        }

        if (t < T_ - 1) {
            // prefetch xg for step t+1 BEFORE the barrier (independent of h)
            float xn[16];
#pragma unroll
            for (int n = 0; n < 4; n++)
#pragma unroll
            for (int rh = 0; rh < 2; rh++) {
                int row = row0 + grp + rh * 8;
                size_t base = ((size_t)row * T_ + (t + 1)) * G4 + n * H_ +
                              hb0 + 2 * tig;
                float2 v = *reinterpret_cast<const float2*>(&xg[base]);
                xn[(n * 2 + rh) * 2]     = v.x;
                xn[(n * 2 + rh) * 2 + 1] = v.y;
            }
            grid_bar_half(t, rowHalf);
#pragma unroll
            for (int i = 0; i < 16; i++) xgv[i] = xn[i];
        }
    }
}

// ---------------- classifier (mma, Wc resident in smem) ----------------
// grid = 128 CTAs (one per batch b), 128 threads (4 warps x 16 bt-rows)
#define CLS_WSTR 1032                         // halfs per Wc smem row
#define CLS_ASTR 136                          // halfs per staged hs row
#define CLS_W_BYTES (24 * CLS_WSTR * 2)       // 49536
#define CLS_A_OFF   CLS_W_BYTES
#define CLS_A_BYTES (2 * 64 * CLS_ASTR * 2)   // 34816
#define CLS_SMEM (CLS_A_OFF + CLS_A_BYTES)    // 84352

__global__ void __launch_bounds__(128, 1)
classifier_mma(const __half* __restrict__ hs,
               const __half* __restrict__ wch,
               const float* __restrict__ bc,
               float* __restrict__ out)
{
    extern __shared__ __align__(16) char csm[];
    const uint32_t csm_u32 = (uint32_t)__cvta_generic_to_shared(csm);
    __half* Wcs = (__half*)csm;

    const int tid = threadIdx.x;
    const int lane = tid & 31, warp = tid >> 5;
    const int b = blockIdx.x;                  // batch index; rows t = 0..63
    const int grp = lane >> 2, tig = lane & 3;
    const int m0 = warp * 16;                  // local t tile

    // load Wc (fp16, padded 24 rows) into smem
    for (int i = tid; i < 24 * (H_ / 2); i += 128) {
        int c = i >> 9, kk = (i & 511) * 2;
        *reinterpret_cast<__half2*>(&Wcs[c * CLS_WSTR + kk]) =
            *reinterpret_cast<const __half2*>(&wch[c * H_ + kk]);
    }

    auto stage = [&](int chunk, int buf) {
        char* dst = csm + CLS_A_OFF + buf * 64 * CLS_ASTR * 2;
        const int p = tid & 15;   // 16B piece
        const int r0 = tid >> 4;  // 0..7
#pragma unroll
        for (int w = 0; w < 8; w++) {
            int t = r0 + w * 8;   // local row = t
            unsigned da = (unsigned)__cvta_generic_to_shared(
                dst + (t * CLS_ASTR + p * 8) * 2);
            asm volatile("cp.async.cg.shared.global [%0], [%1], 16;\n"
                :: "r"(da),
                   "l"(&hs[((size_t)t * B_ + b) * H_ + chunk * 128 + p * 8]));
        }
        asm volatile("cp.async.commit_group;\n");
    };

    const int aRow = m0 + ((lane >> 3) & 1) * 8 + (lane & 7);
    const int aCol = (lane >> 4) * 8;

    float acc[3][4];
#pragma unroll
    for (int n = 0; n < 3; n++)
#pragma unroll
        for (int c = 0; c < 4; c++) acc[n][c] = 0.f;

    stage(0, 0);
    __syncthreads();   // Wcs ready (also covers stage ordering via waits below)

    for (int chunk = 0; chunk < 8; chunk++) {
        if (chunk + 1 < 8) {
            stage(chunk + 1, (chunk + 1) & 1);
            asm volatile("cp.async.wait_group 1;\n");
        } else {
            asm volatile("cp.async.wait_group 0;\n");
        }
        __syncthreads();

        const uint32_t a_b = csm_u32 + CLS_A_OFF + (chunk & 1) * 64 * CLS_ASTR * 2;
#pragma unroll
        for (int j = 0; j < 8; j++) {
            uint32_t a0, a1, a2, a3;
            uint32_t addr = a_b + (aRow * CLS_ASTR + j * 16 + aCol) * 2;
            LDSM4(a0, a1, a2, a3, addr);
            const int kbase = chunk * 128 + j * 16 + 2 * tig;
#pragma unroll
            for (int nt = 0; nt < 3; nt++) {
                int n = nt * 8 + grp;
                uint32_t b0 = *(const uint32_t*)&Wcs[n * CLS_WSTR + kbase];
                uint32_t b1 = *(const uint32_t*)&Wcs[n * CLS_WSTR + kbase + 8];
                mma_f16(acc[nt], a0, a1, a2, a3, b0, b1);
            }
        }
        __syncthreads();
    }

    // epilogue: out[(b*T + t) * C + c]
#pragma unroll
    for (int rh = 0; rh < 2; rh++) {
        int t = m0 + grp + rh * 8;
        size_t obase = ((size_t)b * T_ + t) * C_;
#pragma unroll
        for (int nt = 0; nt < 3; nt++) {
#pragma unroll
            for (int cc = 0; cc < 2; cc++) {
                int col = nt * 8 + 2 * tig + cc;
                if (col < C_)
                    out[obase + col] = acc[nt][rh * 2 + cc] + bc[col];
            }
        }
    }
}

// ---------------- launch ----------------
extern "C" void kernel_launch(void* const* d_in, const int* in_sizes, int n_in,
                              void* d_out, int out_size)
{
    (void)in_sizes; (void)n_in; (void)out_size;
    const float* x    = (const float*)d_in[0];
    const float* W1   = (const float*)d_in[1];
    const float* b1   = (const float*)d_in[2];
    const float* W_ih = (const float*)d_in[3];
    const float* b_ih = (const float*)d_in[4];
    const float* W_hh = (const float*)d_in[5];
    const float* b_hh = (const float*)d_in[6];
    const float* Wc   = (const float*)d_in[7];
    const float* bc   = (const float*)d_in[8];
    float* out = (float*)d_out;

    __half *z_p, *xh_p, *w1h_p, *wih_p, *h_p, *hs_p, *wch_p;
    float *xg_p; unsigned* bar_p;
    cudaGetSymbolAddress((void**)&z_p,   g_z);
    cudaGetSymbolAddress((void**)&xg_p,  g_xg);
    cudaGetSymbolAddress((void**)&h_p,   g_h);
    cudaGetSymbolAddress((void**)&hs_p,  g_hs);
    cudaGetSymbolAddress((void**)&xh_p,  g_xh);
    cudaGetSymbolAddress((void**)&w1h_p, g_w1h);
    cudaGetSymbolAddress((void**)&wih_p, g_wih);
    cudaGetSymbolAddress((void**)&wch_p, g_wch);
    cudaGetSymbolAddress((void**)&bar_p, g_bar);

    cudaMemsetAsync(bar_p, 0, 2 * sizeof(unsigned));
    cudaMemsetAsync(h_p, 0, (size_t)B_ * H_ * sizeof(__half));

    // 0) convert inputs to fp16
    {
        int n4 = B_ * T_ * F_ / 4;
        to_half<<<(n4 + 255) / 256, 256>>>((const float4*)x, (__half2*)xh_p, n4);
        n4 = N_ * F_ / 4;
        to_half<<<(n4 + 255) / 256, 256>>>((const float4*)W1, (__half2*)w1h_p, n4);
        n4 = G4 * N_ / 4;
        to_half<<<(n4 + 255) / 256, 256>>>((const float4*)W_ih, (__half2*)wih_p, n4);
        prep_wc<<<24, 256>>>(Wc, wch_p);
    }

    cudaFuncSetAttribute(gemm_h,
                         cudaFuncAttributeMaxDynamicSharedMemorySize, GEMM_SMEM);

    // 1) z = fp16(relu(x @ W1^T + b1)) : M=8192, N=1024, K=2048
    {
        dim3 grid(N_ / 128, (B_ * T_) / 128);
        gemm_h<<<grid, 256, GEMM_SMEM>>>(xh_p, w1h_p, b1, z_p, N_, F_, 1);
    }
    // 2) xg = z @ W_ih^T + b_ih (fp32 out) : M=8192, N=4096, K=1024
    {
        dim3 grid(G4 / 128, (B_ * T_) / 128);
        gemm_h<<<grid, 256, GEMM_SMEM>>>(z_p, wih_p, b_ih, xg_p, G4, N_, 0);
    }
    // 3) persistent recurrence (fp16 tensor cores, one kernel for all steps)
    cudaFuncSetAttribute(lstm_persistent,
                         cudaFuncAttributeMaxDynamicSharedMemorySize, REC_SMEM);
    lstm_persistent<<<NBLK, 256, REC_SMEM>>>(xg_p, W_hh, b_hh, hs_p);

    // 4) classifier (tensor cores, Wc in smem)
    cudaFuncSetAttribute(classifier_mma,
                         cudaFuncAttributeMaxDynamicSharedMemorySize, CLS_SMEM);
    classifier_mma<<<B_, 128, CLS_SMEM>>>(hs_p, wch_p, bc, out);
}

// round 8
// speedup vs baseline: 11.8928x; 1.0242x over previous
#include <cuda_runtime.h>
#include <cuda_fp16.h>
#include <math.h>
#include <stdint.h>

// Problem constants
#define B_  128
#define T_  64
#define F_  2048
#define N_  1024
#define H_  1024
#define C_  22
#define G4  (4 * H_)   // 4096
#define NBLK 128       // persistent recurrence blocks

// ---------------- scratch (static device globals; no allocation) ----------------
__device__ __half g_z  [(size_t)B_ * T_ * N_];      // [8192, 1024] fp16
__device__ float  g_xg [(size_t)B_ * T_ * G4];      // [B, T, 4096] fp32
__device__ __half g_h  [2][(size_t)B_ * H_];        // ping/pong hidden (fp16)
__device__ __half g_hs [(size_t)T_ * B_ * H_];      // [T, B, H] fp16
__device__ __half g_xh [(size_t)B_ * T_ * F_];      // fp16 x
__device__ __half g_w1h[(size_t)N_ * F_];           // fp16 W1
__device__ __half g_wih[(size_t)G4 * N_];           // fp16 W_ih
__device__ __half g_wch[24 * H_];                   // fp16 Wc padded to 24 rows
__device__ unsigned g_bar[2];                       // per-rowHalf barrier counters

__device__ __forceinline__ float sigmoidf_(float x) {
    return 1.f / (1.f + __expf(-x));
}
__device__ __forceinline__ uint32_t packh2(float a, float b) {
    __half2 h = __floats2half2_rn(a, b);
    return *reinterpret_cast<uint32_t*>(&h);
}
__device__ __forceinline__ void mma_f16(float* acc, uint32_t a0, uint32_t a1,
                                        uint32_t a2, uint32_t a3,
                                        uint32_t b0, uint32_t b1)
{
    asm volatile(
        "mma.sync.aligned.m16n8k16.row.col.f32.f16.f16.f32 "
        "{%0,%1,%2,%3},{%4,%5,%6,%7},{%8,%9},{%0,%1,%2,%3};"
        : "+f"(acc[0]), "+f"(acc[1]), "+f"(acc[2]), "+f"(acc[3])
        : "r"(a0), "r"(a1), "r"(a2), "r"(a3), "r"(b0), "r"(b1));
}
#define LDSM4(r0, r1, r2, r3, addr)                                         \
    asm volatile("ldmatrix.sync.aligned.m8n8.x4.shared.b16 {%0,%1,%2,%3}, [%4];" \
                 : "=r"(r0), "=r"(r1), "=r"(r2), "=r"(r3) : "r"(addr))

// ---------------- fp32 -> fp16 convert ----------------
__global__ void to_half(const float4* __restrict__ in,
                        __half2* __restrict__ out, int n4)
{
    int i = blockIdx.x * blockDim.x + threadIdx.x;
    if (i >= n4) return;
    float4 v = in[i];
    out[2 * i]     = __floats2half2_rn(v.x, v.y);
    out[2 * i + 1] = __floats2half2_rn(v.z, v.w);
}
__global__ void prep_wc(const float* __restrict__ Wc, __half* __restrict__ out)
{
    int c = blockIdx.x;   // 0..23
    for (int k = threadIdx.x; k < H_; k += blockDim.x)
        out[c * H_ + k] = (c < C_) ? __float2half(Wc[(size_t)c * H_ + k])
                                   : __float2half(0.f);
}

// ============================================================================
// fp16 NT GEMM (mma.sync m16n8k16, ldmatrix): C[m,n]=sum_k A[m,k]*B[n,k](+bias)
// BM=BN=128, BK=64 halfs, 256 threads (8 warps 2x4), 3-stage, ONE sync per kb
// epi: 0 = +bias, write fp32 ; 1 = relu(+bias), write fp16
// ============================================================================
#define GBK 64
#define GSTR 72                       // halfs per smem row (144 B, bank-free)
#define GST_BYTES (128 * GSTR * 2)    // 18432 per matrix per stage
#define GSTAGE_BYTES (2 * GST_BYTES)  // 36864
#define GSTAGES 3
#define GEMM_SMEM (GSTAGES * GSTAGE_BYTES)  // 110592

__global__ void __launch_bounds__(256, 2)
gemm_h(const __half* __restrict__ A, const __half* __restrict__ Bw,
       const float* __restrict__ bias, void* __restrict__ Cout,
       int Ntot, int K, int epi)
{
    extern __shared__ __align__(16) char gsm[];
    const uint32_t smem_u32 = (uint32_t)__cvta_generic_to_shared(gsm);

    const int tid = threadIdx.x;
    const int lane = tid & 31, warp = tid >> 5;
    const int bm = blockIdx.y * 128, bn = blockIdx.x * 128;
    const int wm = (warp & 1) * 64, wn = (warp >> 1) * 32;
    const int grp = lane >> 2, tig = lane & 3;
    const int nk = K / GBK;

    // ldmatrix per-lane addressing
    const int aRow = ((lane >> 3) & 1) * 8 + (lane & 7);
    const int aCol = (lane >> 4) * 8;
    const int bRow = (lane & 7) + (lane >> 4) * 8;
    const int bCol = ((lane >> 3) & 1) * 8;

    float acc[4][4][4];
#pragma unroll
    for (int a = 0; a < 4; a++)
#pragma unroll
        for (int b = 0; b < 4; b++)
#pragma unroll
            for (int c = 0; c < 4; c++) acc[a][b][c] = 0.f;

    auto load_stage = [&](int kb, int buf) {
        const int k0 = kb * GBK;
        char* as = gsm + buf * GSTAGE_BYTES;
        char* bs = as + GST_BYTES;
        const int r = tid >> 3, p = tid & 7;   // 128 rows, 8x16B pieces
#pragma unroll
        for (int w = 0; w < 4; w++) {
            int row = r + w * 32;
            unsigned da = (unsigned)__cvta_generic_to_shared(
                as + (row * GSTR + p * 8) * 2);
            asm volatile("cp.async.cg.shared.global [%0], [%1], 16;\n"
                         :: "r"(da), "l"(&A[(size_t)(bm + row) * K + k0 + p * 8]));
            unsigned db = (unsigned)__cvta_generic_to_shared(
                bs + (row * GSTR + p * 8) * 2);
            asm volatile("cp.async.cg.shared.global [%0], [%1], 16;\n"
                         :: "r"(db), "l"(&Bw[(size_t)(bn + row) * K + k0 + p * 8]));
        }
        asm volatile("cp.async.commit_group;\n");
    };

    load_stage(0, 0);
    load_stage(1, 1);

    for (int kb = 0; kb < nk; kb++) {
        if (kb + 1 < nk) asm volatile("cp.async.wait_group 1;\n");
        else             asm volatile("cp.async.wait_group 0;\n");
        __syncthreads();    // all warps done with compute(kb-1); stage kb ready

        if (kb + 2 < nk) load_stage(kb + 2, (kb + 2) % GSTAGES);

        const uint32_t a_b = smem_u32 + (kb % GSTAGES) * GSTAGE_BYTES;
        const uint32_t b_b = a_b + GST_BYTES;
#pragma unroll
        for (int s = 0; s < 4; s++) {
            const int koff = s * 16;
            uint32_t af[4][4], bf[4][2];
#pragma unroll
            for (int mt = 0; mt < 4; mt++) {
                uint32_t addr = a_b +
                    ((wm + mt * 16 + aRow) * GSTR + koff + aCol) * 2;
                LDSM4(af[mt][0], af[mt][1], af[mt][2], af[mt][3], addr);
            }
#pragma unroll
            for (int p = 0; p < 2; p++) {
                uint32_t addr = b_b +
                    ((wn + p * 16 + bRow) * GSTR + koff + bCol) * 2;
                LDSM4(bf[2 * p][0], bf[2 * p][1], bf[2 * p + 1][0],
                      bf[2 * p + 1][1], addr);
            }
#pragma unroll
            for (int mt = 0; mt < 4; mt++)
#pragma unroll
                for (int nt = 0; nt < 4; nt++)
                    mma_f16(acc[mt][nt], af[mt][0], af[mt][1], af[mt][2],
                            af[mt][3], bf[nt][0], bf[nt][1]);
        }
    }

    // epilogue
#pragma unroll
    for (int mt = 0; mt < 4; mt++) {
#pragma unroll
        for (int rh = 0; rh < 2; rh++) {
            int row = bm + wm + mt * 16 + grp + rh * 8;
#pragma unroll
            for (int nt = 0; nt < 4; nt++) {
                int col = bn + wn + nt * 8 + tig * 2;
                float v0 = acc[mt][nt][rh * 2 + 0] + bias[col];
                float v1 = acc[mt][nt][rh * 2 + 1] + bias[col + 1];
                if (epi == 1) {
                    v0 = fmaxf(v0, 0.f);
                    v1 = fmaxf(v1, 0.f);
                    __half* cp = (__half*)Cout;
                    *reinterpret_cast<__half2*>(&cp[(size_t)row * Ntot + col]) =
                        __floats2half2_rn(v0, v1);
                } else {
                    float* cp = (float*)Cout;
                    *reinterpret_cast<float2*>(&cp[(size_t)row * Ntot + col]) =
                        make_float2(v0, v1);
                }
            }
        }
    }
}

// ---------------- persistent LSTM recurrence (fp16, 64 rows x 64 cols) -------
// 256-col chunks (4 per step), single sync per chunk.
#define RT_STRIDE 264                        // halfs per staged row (528 B)
#define WF_SLOTS 16384                       // [k16=64][wg=2][nb=4][lane=32] uint2
#define WF_BYTES (WF_SLOTS * 8)              // 131072
#define HT_OFF   WF_BYTES
#define HT_CHUNK (64 * RT_STRIDE * 2)        // 33792 per buffer
#define HT_BYTES (2 * HT_CHUNK)              // 67584
#define REC_SMEM (WF_BYTES + HT_BYTES)       // 198656

__device__ __forceinline__ void stage_chunk_h(const __half* __restrict__ hsrc,
                                              char* __restrict__ dst,
                                              int chunk, int tid)
{
    const int p = tid & 31;       // 16B piece -> cols p*8..p*8+7 of 256
    const int r0 = tid >> 5;      // 0..7
    const __half* src = hsrc + chunk * 256 + p * 8;
#pragma unroll
    for (int w = 0; w < 8; w++) {
        int row = r0 + w * 8;
        unsigned da = (unsigned)__cvta_generic_to_shared(
            dst + (row * RT_STRIDE + p * 8) * 2);
        asm volatile("cp.async.cg.shared.global [%0], [%1], 16;\n"
                     :: "r"(da), "l"(src + (size_t)row * H_));
    }
    asm volatile("cp.async.commit_group;\n");
}

__device__ __forceinline__ void grid_bar_half(int step, int rowHalf) {
    __syncthreads();
    if (threadIdx.x == 0) {
        __threadfence();
        atomicAdd(&g_bar[rowHalf], 1u);
        const unsigned target = 64u * (step + 1);
        unsigned v;
        do {
            asm volatile("ld.acquire.gpu.global.u32 %0, [%1];"
                         : "=r"(v) : "l"(&g_bar[rowHalf]));
        } while (v < target);
    }
    __syncthreads();
}

__global__ void __launch_bounds__(256, 1)
lstm_persistent(const float* __restrict__ xg,
                const float* __restrict__ W_hh,
                const float* __restrict__ b_hh,
                __half* __restrict__ hs)
{
    extern __shared__ __align__(16) char rsm[];
    uint2* Wf = (uint2*)rsm;                  // [k16][wg][nb][lane]
    const uint32_t rsm_u32 = (uint32_t)__cvta_generic_to_shared(rsm);

    const int tid  = threadIdx.x;
    const int lane = tid & 31;
    const int warp = tid >> 5;                // 0..7
    const int blk  = blockIdx.x;
    const int rowHalf = blk & 1;
    const int colBlk  = blk >> 1;             // 0..63
    const int grp  = lane >> 2;
    const int tig  = lane & 3;
    const int wm   = (warp & 3) * 16;         // local row tile
    const int wg   = warp >> 2;               // hidden group (0/1)
    const int row0 = rowHalf * 64 + wm;       // global batch row base
    const int hb0  = colBlk * 16 + wg * 8;    // hidden base for this warp

    // ldmatrix per-lane addressing for A (h) fragments
    const int aRow = wm + ((lane >> 3) & 1) * 8 + (lane & 7);
    const int aCol = (lane >> 4) * 8;

    // ---- one-time: W_hh slice as fp16 m16n8k16 B fragments ----
    for (int slot = tid; slot < WF_SLOTS; slot += 256) {
        int ls   = slot & 31;
        int idx2 = slot >> 5;
        int nb   = idx2 & 3;
        int wgf  = (idx2 >> 2) & 1;
        int k16  = idx2 >> 3;
        int gs = ls >> 2, ts = ls & 3;
        int gcol = nb * H_ + colBlk * 16 + wgf * 8 + gs;
        const float* wr = &W_hh[(size_t)gcol * H_ + k16 * 16 + 2 * ts];
        Wf[slot] = make_uint2(packh2(wr[0], wr[1]), packh2(wr[8], wr[9]));
    }

    float bh[8];
#pragma unroll
    for (int n = 0; n < 4; n++) {
        int gc = n * H_ + hb0 + 2 * tig;
        bh[2 * n]     = b_hh[gc];
        bh[2 * n + 1] = b_hh[gc + 1];
    }

    float cst[4];
#pragma unroll
    for (int i = 0; i < 4; i++) cst[i] = 0.f;

    // prefetch xg addends for step 0
    float xgv[16];
#pragma unroll
    for (int n = 0; n < 4; n++)
#pragma unroll
    for (int rh = 0; rh < 2; rh++) {
        int row = row0 + grp + rh * 8;
        size_t base = ((size_t)row * T_) * G4 + n * H_ + hb0 + 2 * tig;
        float2 v = *reinterpret_cast<const float2*>(&xg[base]);
        xgv[(n * 2 + rh) * 2]     = v.x;
        xgv[(n * 2 + rh) * 2 + 1] = v.y;
    }

    __syncthreads();

    for (int t = 0; t < T_; t++) {
        const __half* hin  = g_h[t & 1] + (size_t)rowHalf * 64 * H_;
        __half*       hout = g_h[(t + 1) & 1];

        float acc[4][4];
#pragma unroll
        for (int n = 0; n < 4; n++)
#pragma unroll
            for (int c = 0; c < 4; c++) acc[n][c] = 0.f;

        stage_chunk_h(hin, rsm + HT_OFF, 0, tid);

        for (int chunk = 0; chunk < 4; chunk++) {
            asm volatile("cp.async.wait_group 0;\n");
            __syncthreads();   // stage(chunk) visible; all done with prior buf

            if (chunk + 1 < 4)
                stage_chunk_h(hin,
                    rsm + HT_OFF + ((chunk + 1) & 1) * HT_CHUNK,
                    chunk + 1, tid);

            const uint32_t hb_b = rsm_u32 + HT_OFF + (chunk & 1) * HT_CHUNK;
#pragma unroll
            for (int j = 0; j < 16; j++) {
                uint32_t a0, a1, a2, a3;
                uint32_t addr = hb_b + (aRow * RT_STRIDE + j * 16 + aCol) * 2;
                LDSM4(a0, a1, a2, a3, addr);
                const int k16 = chunk * 16 + j;
#pragma unroll
                for (int nb = 0; nb < 4; nb++) {
                    uint2 b = Wf[((k16 * 2 + wg) * 4 + nb) * 32 + lane];
                    mma_f16(acc[nb], a0, a1, a2, a3, b.x, b.y);
                }
            }
        }

        // fused LSTM pointwise (c-state in regs), write h + hs (fp16)
#pragma unroll
        for (int rh = 0; rh < 2; rh++) {
            int row = row0 + grp + rh * 8;
            int hc  = hb0 + 2 * tig;
            float hpair[2];
#pragma unroll
            for (int cc = 0; cc < 2; cc++) {
                int ci = rh * 2 + cc;
                float gi = acc[0][ci] + xgv[(0 * 2 + rh) * 2 + cc] + bh[0 + cc];
                float gf = acc[1][ci] + xgv[(1 * 2 + rh) * 2 + cc] + bh[2 + cc];
                float gg = acc[2][ci] + xgv[(2 * 2 + rh) * 2 + cc] + bh[4 + cc];
                float go = acc[3][ci] + xgv[(3 * 2 + rh) * 2 + cc] + bh[6 + cc];
                float iv = sigmoidf_(gi);
                float fv = sigmoidf_(gf);
                float gv = tanhf(gg);
                float ov = sigmoidf_(go);
                float cn = fv * cst[ci] + iv * gv;
                cst[ci] = cn;
                hpair[cc] = ov * tanhf(cn);
            }
            __half2 hh = __floats2half2_rn(hpair[0], hpair[1]);
            *reinterpret_cast<__half2*>(&hout[(size_t)row * H_ + hc]) = hh;
            *reinterpret_cast<__half2*>(&hs[((size_t)t * B_ + row) * H_ + hc]) = hh;
        }

        if (t < T_ - 1) {
            // prefetch xg for step t+1 BEFORE the barrier (independent of h)
            float xn[16];
#pragma unroll
            for (int n = 0; n < 4; n++)
#pragma unroll
            for (int rh = 0; rh < 2; rh++) {
                int row = row0 + grp + rh * 8;
                size_t base = ((size_t)row * T_ + (t + 1)) * G4 + n * H_ +
                              hb0 + 2 * tig;
                float2 v = *reinterpret_cast<const float2*>(&xg[base]);
                xn[(n * 2 + rh) * 2]     = v.x;
                xn[(n * 2 + rh) * 2 + 1] = v.y;
            }
            grid_bar_half(t, rowHalf);
#pragma unroll
            for (int i = 0; i < 16; i++) xgv[i] = xn[i];
        }
    }
}

// ---------------- classifier (mma, Wc resident in smem) ----------------
#define CLS_WSTR 1032
#define CLS_ASTR 136
#define CLS_W_BYTES (24 * CLS_WSTR * 2)
#define CLS_A_OFF   CLS_W_BYTES
#define CLS_A_BYTES (2 * 64 * CLS_ASTR * 2)
#define CLS_SMEM (CLS_A_OFF + CLS_A_BYTES)

__global__ void __launch_bounds__(128, 1)
classifier_mma(const __half* __restrict__ hs,
               const __half* __restrict__ wch,
               const float* __restrict__ bc,
               float* __restrict__ out)
{
    extern __shared__ __align__(16) char csm[];
    const uint32_t csm_u32 = (uint32_t)__cvta_generic_to_shared(csm);
    __half* Wcs = (__half*)csm;

    const int tid = threadIdx.x;
    const int lane = tid & 31, warp = tid >> 5;
    const int b = blockIdx.x;
    const int grp = lane >> 2, tig = lane & 3;
    const int m0 = warp * 16;

    for (int i = tid; i < 24 * (H_ / 2); i += 128) {
        int c = i >> 9, kk = (i & 511) * 2;
        *reinterpret_cast<__half2*>(&Wcs[c * CLS_WSTR + kk]) =
            *reinterpret_cast<const __half2*>(&wch[c * H_ + kk]);
    }

    auto stage = [&](int chunk, int buf) {
        char* dst = csm + CLS_A_OFF + buf * 64 * CLS_ASTR * 2;
        const int p = tid & 15;
        const int r0 = tid >> 4;
#pragma unroll
        for (int w = 0; w < 8; w++) {
            int t = r0 + w * 8;
            unsigned da = (unsigned)__cvta_generic_to_shared(
                dst + (t * CLS_ASTR + p * 8) * 2);
            asm volatile("cp.async.cg.shared.global [%0], [%1], 16;\n"
                :: "r"(da),
                   "l"(&hs[((size_t)t * B_ + b) * H_ + chunk * 128 + p * 8]));
        }
        asm volatile("cp.async.commit_group;\n");
    };

    const int aRow = m0 + ((lane >> 3) & 1) * 8 + (lane & 7);
    const int aCol = (lane >> 4) * 8;

    float acc[3][4];
#pragma unroll
    for (int n = 0; n < 3; n++)
#pragma unroll
        for (int c = 0; c < 4; c++) acc[n][c] = 0.f;

    stage(0, 0);
    __syncthreads();

    for (int chunk = 0; chunk < 8; chunk++) {
        if (chunk + 1 < 8) {
            stage(chunk + 1, (chunk + 1) & 1);
            asm volatile("cp.async.wait_group 1;\n");
        } else {
            asm volatile("cp.async.wait_group 0;\n");
        }
        __syncthreads();

        const uint32_t a_b = csm_u32 + CLS_A_OFF + (chunk & 1) * 64 * CLS_ASTR * 2;
#pragma unroll
        for (int j = 0; j < 8; j++) {
            uint32_t a0, a1, a2, a3;
            uint32_t addr = a_b + (aRow * CLS_ASTR + j * 16 + aCol) * 2;
            LDSM4(a0, a1, a2, a3, addr);
            const int kbase = chunk * 128 + j * 16 + 2 * tig;
#pragma unroll
            for (int nt = 0; nt < 3; nt++) {
                int n = nt * 8 + grp;
                uint32_t b0 = *(const uint32_t*)&Wcs[n * CLS_WSTR + kbase];
                uint32_t b1 = *(const uint32_t*)&Wcs[n * CLS_WSTR + kbase + 8];
                mma_f16(acc[nt], a0, a1, a2, a3, b0, b1);
            }
        }
        __syncthreads();
    }

#pragma unroll
    for (int rh = 0; rh < 2; rh++) {
        int t = m0 + grp + rh * 8;
        size_t obase = ((size_t)b * T_ + t) * C_;
#pragma unroll
        for (int nt = 0; nt < 3; nt++) {
#pragma unroll
            for (int cc = 0; cc < 2; cc++) {
                int col = nt * 8 + 2 * tig + cc;
                if (col < C_)
                    out[obase + col] = acc[nt][rh * 2 + cc] + bc[col];
            }
        }
    }
}

// ---------------- launch ----------------
extern "C" void kernel_launch(void* const* d_in, const int* in_sizes, int n_in,
                              void* d_out, int out_size)
{
    (void)in_sizes; (void)n_in; (void)out_size;
    const float* x    = (const float*)d_in[0];
    const float* W1   = (const float*)d_in[1];
    const float* b1   = (const float*)d_in[2];
    const float* W_ih = (const float*)d_in[3];
    const float* b_ih = (const float*)d_in[4];
    const float* W_hh = (const float*)d_in[5];
    const float* b_hh = (const float*)d_in[6];
    const float* Wc   = (const float*)d_in[7];
    const float* bc   = (const float*)d_in[8];
    float* out = (float*)d_out;

    __half *z_p, *xh_p, *w1h_p, *wih_p, *h_p, *hs_p, *wch_p;
    float *xg_p; unsigned* bar_p;
    cudaGetSymbolAddress((void**)&z_p,   g_z);
    cudaGetSymbolAddress((void**)&xg_p,  g_xg);
    cudaGetSymbolAddress((void**)&h_p,   g_h);
    cudaGetSymbolAddress((void**)&hs_p,  g_hs);
    cudaGetSymbolAddress((void**)&xh_p,  g_xh);
    cudaGetSymbolAddress((void**)&w1h_p, g_w1h);
    cudaGetSymbolAddress((void**)&wih_p, g_wih);
    cudaGetSymbolAddress((void**)&wch_p, g_wch);
    cudaGetSymbolAddress((void**)&bar_p, g_bar);

    cudaMemsetAsync(bar_p, 0, 2 * sizeof(unsigned));
    cudaMemsetAsync(h_p, 0, (size_t)B_ * H_ * sizeof(__half));

    // 0) convert inputs to fp16
    {
        int n4 = B_ * T_ * F_ / 4;
        to_half<<<(n4 + 255) / 256, 256>>>((const float4*)x, (__half2*)xh_p, n4);
        n4 = N_ * F_ / 4;
        to_half<<<(n4 + 255) / 256, 256>>>((const float4*)W1, (__half2*)w1h_p, n4);
        n4 = G4 * N_ / 4;
        to_half<<<(n4 + 255) / 256, 256>>>((const float4*)W_ih, (__half2*)wih_p, n4);
        prep_wc<<<24, 256>>>(Wc, wch_p);
    }

    cudaFuncSetAttribute(gemm_h,
                         cudaFuncAttributeMaxDynamicSharedMemorySize, GEMM_SMEM);

    // 1) z = fp16(relu(x @ W1^T + b1)) : M=8192, N=1024, K=2048
    {
        dim3 grid(N_ / 128, (B_ * T_) / 128);
        gemm_h<<<grid, 256, GEMM_SMEM>>>(xh_p, w1h_p, b1, z_p, N_, F_, 1);
    }
    // 2) xg = z @ W_ih^T + b_ih (fp32 out) : M=8192, N=4096, K=1024
    {
        dim3 grid(G4 / 128, (B_ * T_) / 128);
        gemm_h<<<grid, 256, GEMM_SMEM>>>(z_p, wih_p, b_ih, xg_p, G4, N_, 0);
    }
    // 3) persistent recurrence
    cudaFuncSetAttribute(lstm_persistent,
                         cudaFuncAttributeMaxDynamicSharedMemorySize, REC_SMEM);
    lstm_persistent<<<NBLK, 256, REC_SMEM>>>(xg_p, W_hh, b_hh, hs_p);

    // 4) classifier
    cudaFuncSetAttribute(classifier_mma,
                         cudaFuncAttributeMaxDynamicSharedMemorySize, CLS_SMEM);
    classifier_mma<<<B_, 128, CLS_SMEM>>>(hs_p, wch_p, bc, out);
}

// round 9
// speedup vs baseline: 11.9259x; 1.0028x over previous
#include <cuda_runtime.h>
#include <cuda_fp16.h>
#include <math.h>
#include <stdint.h>

// Problem constants
#define B_  128
#define T_  64
#define F_  2048
#define N_  1024
#define H_  1024
#define C_  22
#define G4  (4 * H_)   // 4096
#define NBLK 128       // persistent recurrence blocks

// ---------------- scratch (static device globals; no allocation) ----------------
__device__ __half g_z  [(size_t)B_ * T_ * N_];      // [8192, 1024] fp16
__device__ float  g_xg [(size_t)B_ * T_ * G4];      // [B, T, 4096] fp32
__device__ __half g_h0 [(size_t)B_ * H_];           // zero initial hidden (fp16)
__device__ __half g_hs [(size_t)T_ * B_ * H_];      // [T, B, H] fp16 (h history)
__device__ __half g_xh [(size_t)B_ * T_ * F_];      // fp16 x
__device__ __half g_w1h[(size_t)N_ * F_];           // fp16 W1
__device__ __half g_wih[(size_t)G4 * N_];           // fp16 W_ih
__device__ __half g_wch[24 * H_];                   // fp16 Wc padded to 24 rows
__device__ unsigned g_cnt[2][4];                    // [rowHalf][chunk] RAW counters

__device__ __forceinline__ float sigmoidf_(float x) {
    return 1.f / (1.f + __expf(-x));
}
__device__ __forceinline__ uint32_t packh2(float a, float b) {
    __half2 h = __floats2half2_rn(a, b);
    return *reinterpret_cast<uint32_t*>(&h);
}
__device__ __forceinline__ void mma_f16(float* acc, uint32_t a0, uint32_t a1,
                                        uint32_t a2, uint32_t a3,
                                        uint32_t b0, uint32_t b1)
{
    asm volatile(
        "mma.sync.aligned.m16n8k16.row.col.f32.f16.f16.f32 "
        "{%0,%1,%2,%3},{%4,%5,%6,%7},{%8,%9},{%0,%1,%2,%3};"
        : "+f"(acc[0]), "+f"(acc[1]), "+f"(acc[2]), "+f"(acc[3])
        : "r"(a0), "r"(a1), "r"(a2), "r"(a3), "r"(b0), "r"(b1));
}
#define LDSM4(r0, r1, r2, r3, addr)                                         \
    asm volatile("ldmatrix.sync.aligned.m8n8.x4.shared.b16 {%0,%1,%2,%3}, [%4];" \
                 : "=r"(r0), "=r"(r1), "=r"(r2), "=r"(r3) : "r"(addr))

// ---------------- fp32 -> fp16 convert ----------------
__global__ void to_half(const float4* __restrict__ in,
                        __half2* __restrict__ out, int n4)
{
    int i = blockIdx.x * blockDim.x + threadIdx.x;
    if (i >= n4) return;
    float4 v = in[i];
    out[2 * i]     = __floats2half2_rn(v.x, v.y);
    out[2 * i + 1] = __floats2half2_rn(v.z, v.w);
}
__global__ void prep_wc(const float* __restrict__ Wc, __half* __restrict__ out)
{
    int c = blockIdx.x;   // 0..23
    for (int k = threadIdx.x; k < H_; k += blockDim.x)
        out[c * H_ + k] = (c < C_) ? __float2half(Wc[(size_t)c * H_ + k])
                                   : __float2half(0.f);
}

// ============================================================================
// fp16 NT GEMM (mma.sync m16n8k16, ldmatrix): C[m,n]=sum_k A[m,k]*B[n,k](+bias)
// BM=BN=128, BK=64 halfs, 256 threads (8 warps 2x4), 3-stage, ONE sync per kb
// epi: 0 = +bias, write fp32 ; 1 = relu(+bias), write fp16
// ============================================================================
#define GBK 64
#define GSTR 72                       // halfs per smem row (144 B, bank-free)
#define GST_BYTES (128 * GSTR * 2)    // 18432 per matrix per stage
#define GSTAGE_BYTES (2 * GST_BYTES)  // 36864
#define GSTAGES 3
#define GEMM_SMEM (GSTAGES * GSTAGE_BYTES)  // 110592

__global__ void __launch_bounds__(256, 2)
gemm_h(const __half* __restrict__ A, const __half* __restrict__ Bw,
       const float* __restrict__ bias, void* __restrict__ Cout,
       int Ntot, int K, int epi)
{
    extern __shared__ __align__(16) char gsm[];
    const uint32_t smem_u32 = (uint32_t)__cvta_generic_to_shared(gsm);

    const int tid = threadIdx.x;
    const int lane = tid & 31, warp = tid >> 5;
    const int bm = blockIdx.y * 128, bn = blockIdx.x * 128;
    const int wm = (warp & 1) * 64, wn = (warp >> 1) * 32;
    const int grp = lane >> 2, tig = lane & 3;
    const int nk = K / GBK;

    // ldmatrix per-lane addressing
    const int aRow = ((lane >> 3) & 1) * 8 + (lane & 7);
    const int aCol = (lane >> 4) * 8;
    const int bRow = (lane & 7) + (lane >> 4) * 8;
    const int bCol = ((lane >> 3) & 1) * 8;

    float acc[4][4][4];
#pragma unroll
    for (int a = 0; a < 4; a++)
#pragma unroll
        for (int b = 0; b < 4; b++)
#pragma unroll
            for (int c = 0; c < 4; c++) acc[a][b][c] = 0.f;

    auto load_stage = [&](int kb, int buf) {
        const int k0 = kb * GBK;
        char* as = gsm + buf * GSTAGE_BYTES;
        char* bs = as + GST_BYTES;
        const int r = tid >> 3, p = tid & 7;   // 128 rows, 8x16B pieces
#pragma unroll
        for (int w = 0; w < 4; w++) {
            int row = r + w * 32;
            unsigned da = (unsigned)__cvta_generic_to_shared(
                as + (row * GSTR + p * 8) * 2);
            asm volatile("cp.async.cg.shared.global [%0], [%1], 16;\n"
                         :: "r"(da), "l"(&A[(size_t)(bm + row) * K + k0 + p * 8]));
            unsigned db = (unsigned)__cvta_generic_to_shared(
                bs + (row * GSTR + p * 8) * 2);
            asm volatile("cp.async.cg.shared.global [%0], [%1], 16;\n"
                         :: "r"(db), "l"(&Bw[(size_t)(bn + row) * K + k0 + p * 8]));
        }
        asm volatile("cp.async.commit_group;\n");
    };

    load_stage(0, 0);
    load_stage(1, 1);

    for (int kb = 0; kb < nk; kb++) {
        if (kb + 1 < nk) asm volatile("cp.async.wait_group 1;\n");
        else             asm volatile("cp.async.wait_group 0;\n");
        __syncthreads();    // all warps done with compute(kb-1); stage kb ready

        if (kb + 2 < nk) load_stage(kb + 2, (kb + 2) % GSTAGES);

        const uint32_t a_b = smem_u32 + (kb % GSTAGES) * GSTAGE_BYTES;
        const uint32_t b_b = a_b + GST_BYTES;
#pragma unroll
        for (int s = 0; s < 4; s++) {
            const int koff = s * 16;
            uint32_t af[4][4], bf[4][2];
#pragma unroll
            for (int mt = 0; mt < 4; mt++) {
                uint32_t addr = a_b +
                    ((wm + mt * 16 + aRow) * GSTR + koff + aCol) * 2;
                LDSM4(af[mt][0], af[mt][1], af[mt][2], af[mt][3], addr);
            }
#pragma unroll
            for (int p = 0; p < 2; p++) {
                uint32_t addr = b_b +
                    ((wn + p * 16 + bRow) * GSTR + koff + bCol) * 2;
                LDSM4(bf[2 * p][0], bf[2 * p][1], bf[2 * p + 1][0],
                      bf[2 * p + 1][1], addr);
            }
#pragma unroll
            for (int mt = 0; mt < 4; mt++)
#pragma unroll
                for (int nt = 0; nt < 4; nt++)
                    mma_f16(acc[mt][nt], af[mt][0], af[mt][1], af[mt][2],
                            af[mt][3], bf[nt][0], bf[nt][1]);
        }
    }

    // epilogue
#pragma unroll
    for (int mt = 0; mt < 4; mt++) {
#pragma unroll
        for (int rh = 0; rh < 2; rh++) {
            int row = bm + wm + mt * 16 + grp + rh * 8;
#pragma unroll
            for (int nt = 0; nt < 4; nt++) {
                int col = bn + wn + nt * 8 + tig * 2;
                float v0 = acc[mt][nt][rh * 2 + 0] + bias[col];
                float v1 = acc[mt][nt][rh * 2 + 1] + bias[col + 1];
                if (epi == 1) {
                    v0 = fmaxf(v0, 0.f);
                    v1 = fmaxf(v1, 0.f);
                    __half* cp = (__half*)Cout;
                    *reinterpret_cast<__half2*>(&cp[(size_t)row * Ntot + col]) =
                        __floats2half2_rn(v0, v1);
                } else {
                    float* cp = (float*)Cout;
                    *reinterpret_cast<float2*>(&cp[(size_t)row * Ntot + col]) =
                        make_float2(v0, v1);
                }
            }
        }
    }
}

// ---------------- persistent LSTM recurrence (fp16, 64 rows x 64 cols) -------
// h history lives in g_hs (read h(t-1) = hs[t-1], write h(t) = hs[t]).
// RAW sync: per-chunk counters cnt[rowHalf][chunk]; chunk = 256 hidden cols
// = 16 producer CTAs. No WAR hazard (history), so no full barrier.
#define RT_STRIDE 264                        // halfs per staged row (528 B)
#define WF_SLOTS 16384                       // [k16=64][wg=2][nb=4][lane=32] uint2
#define WF_BYTES (WF_SLOTS * 8)              // 131072
#define HT_OFF   WF_BYTES
#define HT_CHUNK (64 * RT_STRIDE * 2)        // 33792 per buffer
#define HT_BYTES (2 * HT_CHUNK)              // 67584
#define REC_SMEM (WF_BYTES + HT_BYTES)       // 198656

__device__ __forceinline__ void stage_chunk_h(const __half* __restrict__ hsrc,
                                              char* __restrict__ dst,
                                              int chunk, int tid)
{
    const int p = tid & 31;       // 16B piece -> cols p*8..p*8+7 of 256
    const int r0 = tid >> 5;      // 0..7
    const __half* src = hsrc + chunk * 256 + p * 8;
#pragma unroll
    for (int w = 0; w < 8; w++) {
        int row = r0 + w * 8;
        unsigned da = (unsigned)__cvta_generic_to_shared(
            dst + (row * RT_STRIDE + p * 8) * 2);
        asm volatile("cp.async.cg.shared.global [%0], [%1], 16;\n"
                     :: "r"(da), "l"(src + (size_t)row * H_));
    }
    asm volatile("cp.async.commit_group;\n");
}

// thread0 acquire-poll until counter >= target (caller must __syncthreads after)
__device__ __forceinline__ void wait_cnt(const unsigned* p, unsigned target) {
    if (threadIdx.x == 0) {
        unsigned v;
        do {
            asm volatile("ld.acquire.gpu.global.u32 %0, [%1];"
                         : "=r"(v) : "l"(p));
        } while (v < target);
    }
}

__global__ void __launch_bounds__(256, 1)
lstm_persistent(const float* __restrict__ xg,
                const float* __restrict__ W_hh,
                const float* __restrict__ b_hh,
                const __half* __restrict__ h0,
                __half* __restrict__ hs)
{
    extern __shared__ __align__(16) char rsm[];
    uint2* Wf = (uint2*)rsm;                  // [k16][wg][nb][lane]
    const uint32_t rsm_u32 = (uint32_t)__cvta_generic_to_shared(rsm);

    const int tid  = threadIdx.x;
    const int lane = tid & 31;
    const int warp = tid >> 5;                // 0..7
    const int blk  = blockIdx.x;
    const int rowHalf = blk & 1;
    const int colBlk  = blk >> 1;             // 0..63
    const int grp  = lane >> 2;
    const int tig  = lane & 3;
    const int wm   = (warp & 3) * 16;         // local row tile
    const int wg   = warp >> 2;               // hidden group (0/1)
    const int row0 = rowHalf * 64 + wm;       // global batch row base
    const int hb0  = colBlk * 16 + wg * 8;    // hidden base for this warp
    const int myChunk = colBlk >> 4;          // which chunk this CTA produces

    // ldmatrix per-lane addressing for A (h) fragments
    const int aRow = wm + ((lane >> 3) & 1) * 8 + (lane & 7);
    const int aCol = (lane >> 4) * 8;

    // ---- one-time: W_hh slice as fp16 m16n8k16 B fragments ----
    for (int slot = tid; slot < WF_SLOTS; slot += 256) {
        int ls   = slot & 31;
        int idx2 = slot >> 5;
        int nb   = idx2 & 3;
        int wgf  = (idx2 >> 2) & 1;
        int k16  = idx2 >> 3;
        int gs = ls >> 2, ts = ls & 3;
        int gcol = nb * H_ + colBlk * 16 + wgf * 8 + gs;
        const float* wr = &W_hh[(size_t)gcol * H_ + k16 * 16 + 2 * ts];
        Wf[slot] = make_uint2(packh2(wr[0], wr[1]), packh2(wr[8], wr[9]));
    }

    float bh[8];
#pragma unroll
    for (int n = 0; n < 4; n++) {
        int gc = n * H_ + hb0 + 2 * tig;
        bh[2 * n]     = b_hh[gc];
        bh[2 * n + 1] = b_hh[gc + 1];
    }

    float cst[4];
#pragma unroll
    for (int i = 0; i < 4; i++) cst[i] = 0.f;

    __syncthreads();

    for (int t = 0; t < T_; t++) {
        const __half* hsrc = (t == 0)
            ? h0 + (size_t)rowHalf * 64 * H_
            : hs + ((size_t)(t - 1) * B_ + rowHalf * 64) * H_;

        // xg addends for this step (used ~5us later in pointwise)
        float xgv[16];
#pragma unroll
        for (int n = 0; n < 4; n++)
#pragma unroll
        for (int rh = 0; rh < 2; rh++) {
            int row = row0 + grp + rh * 8;
            size_t base = ((size_t)row * T_ + t) * G4 + n * H_ + hb0 + 2 * tig;
            float2 v = *reinterpret_cast<const float2*>(&xg[base]);
            xgv[(n * 2 + rh) * 2]     = v.x;
            xgv[(n * 2 + rh) * 2 + 1] = v.y;
        }

        float acc[4][4];
#pragma unroll
        for (int n = 0; n < 4; n++)
#pragma unroll
            for (int c = 0; c < 4; c++) acc[n][c] = 0.f;

        // RAW wait for chunk 0 producers, then stage it
        if (t > 0) wait_cnt(&g_cnt[rowHalf][0], 16u * (unsigned)t);
        __syncthreads();
        stage_chunk_h(hsrc, rsm + HT_OFF, 0, tid);

        for (int chunk = 0; chunk < 4; chunk++) {
            if (chunk + 1 < 4 && t > 0)
                wait_cnt(&g_cnt[rowHalf][chunk + 1], 16u * (unsigned)t);
            asm volatile("cp.async.wait_group 0;\n");
            __syncthreads();   // stage(chunk) visible; poll broadcast; buf free

            if (chunk + 1 < 4)
                stage_chunk_h(hsrc,
                    rsm + HT_OFF + ((chunk + 1) & 1) * HT_CHUNK,
                    chunk + 1, tid);

            const uint32_t hb_b = rsm_u32 + HT_OFF + (chunk & 1) * HT_CHUNK;
#pragma unroll
            for (int j = 0; j < 16; j++) {
                uint32_t a0, a1, a2, a3;
                uint32_t addr = hb_b + (aRow * RT_STRIDE + j * 16 + aCol) * 2;
                LDSM4(a0, a1, a2, a3, addr);
                const int k16 = chunk * 16 + j;
#pragma unroll
                for (int nb = 0; nb < 4; nb++) {
                    uint2 b = Wf[((k16 * 2 + wg) * 4 + nb) * 32 + lane];
                    mma_f16(acc[nb], a0, a1, a2, a3, b.x, b.y);
                }
            }
        }

        // fused LSTM pointwise (c-state in regs), write h(t) into hs[t]
#pragma unroll
        for (int rh = 0; rh < 2; rh++) {
            int row = row0 + grp + rh * 8;
            int hc  = hb0 + 2 * tig;
            float hpair[2];
#pragma unroll
            for (int cc = 0; cc < 2; cc++) {
                int ci = rh * 2 + cc;
                float gi = acc[0][ci] + xgv[(0 * 2 + rh) * 2 + cc] + bh[0 + cc];
                float gf = acc[1][ci] + xgv[(1 * 2 + rh) * 2 + cc] + bh[2 + cc];
                float gg = acc[2][ci] + xgv[(2 * 2 + rh) * 2 + cc] + bh[4 + cc];
                float go = acc[3][ci] + xgv[(3 * 2 + rh) * 2 + cc] + bh[6 + cc];
                float iv = sigmoidf_(gi);
                float fv = sigmoidf_(gf);
                float gv = tanhf(gg);
                float ov = sigmoidf_(go);
                float cn = fv * cst[ci] + iv * gv;
                cst[ci] = cn;
                hpair[cc] = ov * tanhf(cn);
            }
            __half2 hh = __floats2half2_rn(hpair[0], hpair[1]);
            *reinterpret_cast<__half2*>(&hs[((size_t)t * B_ + row) * H_ + hc]) = hh;
        }

        // release-signal: this CTA's 16 cols of hs[t] are written
        __syncthreads();
        if (tid == 0) {
            __threadfence();
            atomicAdd(&g_cnt[rowHalf][myChunk], 1u);
        }
    }
}

// ---------------- classifier (mma, Wc resident in smem) ----------------
#define CLS_WSTR 1032
#define CLS_ASTR 136
#define CLS_W_BYTES (24 * CLS_WSTR * 2)
#define CLS_A_OFF   CLS_W_BYTES
#define CLS_A_BYTES (2 * 64 * CLS_ASTR * 2)
#define CLS_SMEM (CLS_A_OFF + CLS_A_BYTES)

__global__ void __launch_bounds__(128, 1)
classifier_mma(const __half* __restrict__ hs,
               const __half* __restrict__ wch,
               const float* __restrict__ bc,
               float* __restrict__ out)
{
    extern __shared__ __align__(16) char csm[];
    const uint32_t csm_u32 = (uint32_t)__cvta_generic_to_shared(csm);
    __half* Wcs = (__half*)csm;

    const int tid = threadIdx.x;
    const int lane = tid & 31, warp = tid >> 5;
    const int b = blockIdx.x;
    const int grp = lane >> 2, tig = lane & 3;
    const int m0 = warp * 16;

    for (int i = tid; i < 24 * (H_ / 2); i += 128) {
        int c = i >> 9, kk = (i & 511) * 2;
        *reinterpret_cast<__half2*>(&Wcs[c * CLS_WSTR + kk]) =
            *reinterpret_cast<const __half2*>(&wch[c * H_ + kk]);
    }

    auto stage = [&](int chunk, int buf) {
        char* dst = csm + CLS_A_OFF + buf * 64 * CLS_ASTR * 2;
        const int p = tid & 15;
        const int r0 = tid >> 4;
#pragma unroll
        for (int w = 0; w < 8; w++) {
            int t = r0 + w * 8;
            unsigned da = (unsigned)__cvta_generic_to_shared(
                dst + (t * CLS_ASTR + p * 8) * 2);
            asm volatile("cp.async.cg.shared.global [%0], [%1], 16;\n"
                :: "r"(da),
                   "l"(&hs[((size_t)t * B_ + b) * H_ + chunk * 128 + p * 8]));
        }
        asm volatile("cp.async.commit_group;\n");
    };

    const int aRow = m0 + ((lane >> 3) & 1) * 8 + (lane & 7);
    const int aCol = (lane >> 4) * 8;

    float acc[3][4];
#pragma unroll
    for (int n = 0; n < 3; n++)
#pragma unroll
        for (int c = 0; c < 4; c++) acc[n][c] = 0.f;

    stage(0, 0);
    __syncthreads();

    for (int chunk = 0; chunk < 8; chunk++) {
        if (chunk + 1 < 8) {
            stage(chunk + 1, (chunk + 1) & 1);
            asm volatile("cp.async.wait_group 1;\n");
        } else {
            asm volatile("cp.async.wait_group 0;\n");
        }
        __syncthreads();

        const uint32_t a_b = csm_u32 + CLS_A_OFF + (chunk & 1) * 64 * CLS_ASTR * 2;
#pragma unroll
        for (int j = 0; j < 8; j++) {
            uint32_t a0, a1, a2, a3;
            uint32_t addr = a_b + (aRow * CLS_ASTR + j * 16 + aCol) * 2;
            LDSM4(a0, a1, a2, a3, addr);
            const int kbase = chunk * 128 + j * 16 + 2 * tig;
#pragma unroll
            for (int nt = 0; nt < 3; nt++) {
                int n = nt * 8 + grp;
                uint32_t b0 = *(const uint32_t*)&Wcs[n * CLS_WSTR + kbase];
                uint32_t b1 = *(const uint32_t*)&Wcs[n * CLS_WSTR + kbase + 8];
                mma_f16(acc[nt], a0, a1, a2, a3, b0, b1);
            }
        }
        __syncthreads();
    }

#pragma unroll
    for (int rh = 0; rh < 2; rh++) {
        int t = m0 + grp + rh * 8;
        size_t obase = ((size_t)b * T_ + t) * C_;
#pragma unroll
        for (int nt = 0; nt < 3; nt++) {
#pragma unroll
            for (int cc = 0; cc < 2; cc++) {
                int col = nt * 8 + 2 * tig + cc;
                if (col < C_)
                    out[obase + col] = acc[nt][rh * 2 + cc] + bc[col];
            }
        }
    }
}

// ---------------- launch ----------------
extern "C" void kernel_launch(void* const* d_in, const int* in_sizes, int n_in,
                              void* d_out, int out_size)
{
    (void)in_sizes; (void)n_in; (void)out_size;
    const float* x    = (const float*)d_in[0];
    const float* W1   = (const float*)d_in[1];
    const float* b1   = (const float*)d_in[2];
    const float* W_ih = (const float*)d_in[3];
    const float* b_ih = (const float*)d_in[4];
    const float* W_hh = (const float*)d_in[5];
    const float* b_hh = (const float*)d_in[6];
    const float* Wc   = (const float*)d_in[7];
    const float* bc   = (const float*)d_in[8];
    float* out = (float*)d_out;

    __half *z_p, *xh_p, *w1h_p, *wih_p, *h0_p, *hs_p, *wch_p;
    float *xg_p; unsigned* cnt_p;
    cudaGetSymbolAddress((void**)&z_p,   g_z);
    cudaGetSymbolAddress((void**)&xg_p,  g_xg);
    cudaGetSymbolAddress((void**)&h0_p,  g_h0);
    cudaGetSymbolAddress((void**)&hs_p,  g_hs);
    cudaGetSymbolAddress((void**)&xh_p,  g_xh);
    cudaGetSymbolAddress((void**)&w1h_p, g_w1h);
    cudaGetSymbolAddress((void**)&wih_p, g_wih);
    cudaGetSymbolAddress((void**)&wch_p, g_wch);
    cudaGetSymbolAddress((void**)&cnt_p, g_cnt);

    cudaMemsetAsync(cnt_p, 0, 8 * sizeof(unsigned));
    cudaMemsetAsync(h0_p, 0, (size_t)B_ * H_ * sizeof(__half));

    // 0) convert inputs to fp16
    {
        int n4 = B_ * T_ * F_ / 4;
        to_half<<<(n4 + 255) / 256, 256>>>((const float4*)x, (__half2*)xh_p, n4);
        n4 = N_ * F_ / 4;
        to_half<<<(n4 + 255) / 256, 256>>>((const float4*)W1, (__half2*)w1h_p, n4);
        n4 = G4 * N_ / 4;
        to_half<<<(n4 + 255) / 256, 256>>>((const float4*)W_ih, (__half2*)wih_p, n4);
        prep_wc<<<24, 256>>>(Wc, wch_p);
    }

    cudaFuncSetAttribute(gemm_h,
                         cudaFuncAttributeMaxDynamicSharedMemorySize, GEMM_SMEM);

    // 1) z = fp16(relu(x @ W1^T + b1)) : M=8192, N=1024, K=2048
    {
        dim3 grid(N_ / 128, (B_ * T_) / 128);
        gemm_h<<<grid, 256, GEMM_SMEM>>>(xh_p, w1h_p, b1, z_p, N_, F_, 1);
    }
    // 2) xg = z @ W_ih^T + b_ih (fp32 out) : M=8192, N=4096, K=1024
    {
        dim3 grid(G4 / 128, (B_ * T_) / 128);
        gemm_h<<<grid, 256, GEMM_SMEM>>>(z_p, wih_p, b_ih, xg_p, G4, N_, 0);
    }
    // 3) persistent recurrence (RAW-signaled, no grid barrier)
    cudaFuncSetAttribute(lstm_persistent,
                         cudaFuncAttributeMaxDynamicSharedMemorySize, REC_SMEM);
    lstm_persistent<<<NBLK, 256, REC_SMEM>>>(xg_p, W_hh, b_hh, h0_p, hs_p);

    // 4) classifier
    cudaFuncSetAttribute(classifier_mma,
                         cudaFuncAttributeMaxDynamicSharedMemorySize, CLS_SMEM);
    classifier_mma<<<B_, 128, CLS_SMEM>>>(hs_p, wch_p, bc, out);
}